// round 13
// baseline (speedup 1.0000x reference)
#include <cuda_runtime.h>
#include <math.h>
#include <stdint.h>

// ---------------- problem constants ----------------
#define BB 128
#define CC 3
#define IMG 224
#define PP 16
#define HP 14
#define NP 196
#define SS 197
#define DD 384
#define HEADS 6
#define HD 64
#define DEPTH 12
#define HID 1536
#define NCLS 100
#define PATCH_DIM 768
#define TOK (BB*SS)    // 25216
#define PTOK (BB*NP)   // 25088
#define BH (BB*HEADS)  // 768
#define SSP 224        // padded seq = 7 chunks * 32 (covers all prep writes)

// ---------------- scratch ----------------
__device__ float g_patches[PTOK * PATCH_DIM];
__device__ float g_tok[PTOK * DD];
__device__ float g_h[TOK * DD];
__device__ float g_xn[TOK * DD];
__device__ float g_qkv[TOK * 3 * DD];
__device__ float g_ctx[TOK * DD];
__device__ float g_hid[TOK * HID];
__device__ float g_cls[BB * DD];
// pre-split K / V^T (per current layer)
__device__ float g_khi[(size_t)BH * SSP * HD];
__device__ float g_klo[(size_t)BH * SSP * HD];
__device__ float g_vthi[(size_t)BH * HD * SSP];
__device__ float g_vtlo[(size_t)BH * HD * SSP];
// tf32-rounded weights (offsets in floats)
#define W_PATCH 0
#define W_QKV   294912
#define W_OUT   5603328
#define W_FC1   7372800
#define W_FC2   14450688
#define W_TOTAL 21528576
__device__ float g_w[W_TOTAL];

// ---------------- helpers ----------------
__device__ __forceinline__ float tf32r(float x) {
    uint32_t u;
    asm("cvt.rna.tf32.f32 %0, %1;" : "=r"(u) : "f"(x));
    return __uint_as_float(u);
}
__device__ __forceinline__ void split_u(float x, uint32_t& hi, uint32_t& lo) {
    float h = tf32r(x);
    hi = __float_as_uint(h);
    lo = __float_as_uint(tf32r(x - h));
}
__device__ __forceinline__ void split_f(float x, float& hi, float& lo) {
    hi = tf32r(x);
    lo = tf32r(x - hi);
}
__device__ __forceinline__ uint32_t smem_u32(const void* p) {
    return (uint32_t)__cvta_generic_to_shared(p);
}
#define CPA(dst, src) asm volatile("cp.async.cg.shared.global [%0], [%1], 16;" :: "r"(dst), "l"(src))
#define CPC() asm volatile("cp.async.commit_group;")
#define CPW0() asm volatile("cp.async.wait_group 0;")
#define CPW1() asm volatile("cp.async.wait_group 1;")
#define MMA_TF32(d, a, b) asm volatile( \
    "mma.sync.aligned.m16n8k8.row.col.f32.tf32.tf32.f32 " \
    "{%0,%1,%2,%3},{%4,%5,%6,%7},{%8,%9},{%0,%1,%2,%3};" \
    : "+f"(d[0]), "+f"(d[1]), "+f"(d[2]), "+f"(d[3]) \
    : "r"(a[0]), "r"(a[1]), "r"(a[2]), "r"(a[3]), "r"(b[0]), "r"(b[1]))
#define MMA_TF32_2(d, a, b0v, b1v) asm volatile( \
    "mma.sync.aligned.m16n8k8.row.col.f32.tf32.tf32.f32 " \
    "{%0,%1,%2,%3},{%4,%5,%6,%7},{%8,%9},{%0,%1,%2,%3};" \
    : "+f"(d[0]), "+f"(d[1]), "+f"(d[2]), "+f"(d[3]) \
    : "r"(a[0]), "r"(a[1]), "r"(a[2]), "r"(a[3]), "r"(b0v), "r"(b1v))
#define LDSM_X4(f, addr) asm volatile( \
    "ldmatrix.sync.aligned.m8n8.x4.shared.b16 {%0,%1,%2,%3}, [%4];" \
    : "=r"((f)[0]), "=r"((f)[1]), "=r"((f)[2]), "=r"((f)[3]) : "r"(addr))

// ---------------- weight rounding (2 launches for profiler indexing) ----------------
__global__ void round_w_a(const float* __restrict__ pw, const float* __restrict__ qw,
                          const float* __restrict__ ow, float* __restrict__ w) {
    int i = blockIdx.x * blockDim.x + threadIdx.x;
    if (i >= W_FC1 / 4) return;
    int f = i * 4;
    const float* src; int off;
    if (f < W_QKV)      { src = pw; off = f - W_PATCH; }
    else if (f < W_OUT) { src = qw; off = f - W_QKV; }
    else                { src = ow; off = f - W_OUT; }
    float4 v = *(const float4*)(src + off);
    v.x = tf32r(v.x); v.y = tf32r(v.y); v.z = tf32r(v.z); v.w = tf32r(v.w);
    ((float4*)w)[i] = v;
}
__global__ void round_w_b(const float* __restrict__ f1, const float* __restrict__ f2,
                          float* __restrict__ w) {
    int i = blockIdx.x * blockDim.x + threadIdx.x;
    if (i >= (W_TOTAL - W_FC1) / 4) return;
    int f = W_FC1 + i * 4;
    const float* src; int off;
    if (f < W_FC2) { src = f1; off = f - W_FC1; }
    else           { src = f2; off = f - W_FC2; }
    float4 v = *(const float4*)(src + off);
    v.x = tf32r(v.x); v.y = tf32r(v.y); v.z = tf32r(v.z); v.w = tf32r(v.w);
    ((float4*)(w + W_FC1))[i] = v;
}

// ---------------- patchify (+tf32 round) ----------------
__global__ void patchify_kernel(const float* __restrict__ x, float* __restrict__ patches) {
    int idx = blockIdx.x * blockDim.x + threadIdx.x;
    if (idx >= PTOK * PATCH_DIM) return;
    int t = idx / PATCH_DIM;
    int k = idx - t * PATCH_DIM;
    int b = t / NP;
    int n = t - b * NP;
    int ph = n / HP, pw = n - ph * HP;
    int c = k >> 8;
    int py = (k >> 4) & 15;
    int px = k & 15;
    patches[idx] = tf32r(x[(((size_t)b * CC + c) * IMG + (ph * PP + py)) * IMG + (pw * PP + px)]);
}

// ---------------- assemble h = [cls; tok] + pos ----------------
__global__ void assemble_kernel(const float* __restrict__ tok, const float* __restrict__ cls_token,
                                const float* __restrict__ pos, float* __restrict__ h) {
    int idx = blockIdx.x * blockDim.x + threadIdx.x;
    if (idx >= TOK * DD) return;
    int row = idx / DD;
    int d = idx - row * DD;
    int b = row / SS;
    int s = row - b * SS;
    float v = (s == 0) ? cls_token[d] : tok[((size_t)b * NP + (s - 1)) * DD + d];
    h[idx] = v + pos[s * DD + d];
}

// ---------------- tf32 NT GEMM (unchanged) ----------------
#define GSTAGE 4096
#define GEMM_SMEM (3 * 2 * GSTAGE * 4)      // 98304 B

template <int OP>
__global__ void __launch_bounds__(256, 2) gemm_tf32(
    const float* __restrict__ A, const float* __restrict__ Bw,
    const float* __restrict__ bias, const float* __restrict__ res,
    float* __restrict__ C, int M, int N, int K)
{
    extern __shared__ float gsm[];
    float* As = gsm;
    float* Bs = gsm + 3 * GSTAGE;

    const int tid = threadIdx.x;
    const int lane = tid & 31, warp = tid >> 5;
    const int wm = (warp >> 1) * 32;
    const int wn = (warp & 1) * 64;
    const int r = lane >> 2, cq = lane & 3;
    const int m0 = blockIdx.y * 128, n0 = blockIdx.x * 128;

    const int lr = tid >> 3;
    const int lc = (tid & 7) * 4;
    const int sw = (lr & 7) * 4;
    const float* Ag = A + (size_t)(m0 + lr) * K + lc;
    const float* Bg = Bw + (size_t)(n0 + lr) * K + lc;
    uint32_t sA[3][4], sB[3][4];
#pragma unroll
    for (int s = 0; s < 3; s++)
#pragma unroll
        for (int c = 0; c < 4; c++) {
            sA[s][c] = smem_u32(As + (size_t)s * GSTAGE + (lr + c * 32) * 32 + (lc ^ sw));
            sB[s][c] = smem_u32(Bs + (size_t)s * GSTAGE + (lr + c * 32) * 32 + (lc ^ sw));
        }

    const int lm = lane >> 3;
    const int rit = lane & 7;
    const int arow0 = wm + ((lm & 1) * 8) + rit;
    const int abo = lm >> 1;
    const uint32_t aswz0 = (uint32_t)(arow0 & 7);
    const uint32_t aswz1 = (uint32_t)((arow0 + 16) & 7);
    const int bnt = lm >> 1;
    const int bbo = lm & 1;
    uint32_t browoff[4], bswz[4];
#pragma unroll
    for (int g = 0; g < 4; g++) {
        int brow = wn + (2 * g + bnt) * 8 + rit;
        browoff[g] = (uint32_t)(brow * 128);
        bswz[g] = (uint32_t)(brow & 7);
    }
    const uint32_t smemA0 = smem_u32(As);
    const uint32_t smemB0 = smem_u32(Bs);

    float acc[2][8][4];
#pragma unroll
    for (int mt = 0; mt < 2; mt++)
#pragma unroll
        for (int nt = 0; nt < 8; nt++)
#pragma unroll
            for (int i = 0; i < 4; i++) acc[mt][nt][i] = 0.f;

    const int KT = K / 32;
#pragma unroll
    for (int c = 0; c < 4; c++) {
        CPA(sA[0][c], Ag + (size_t)c * 32 * K);
        CPA(sB[0][c], Bg + (size_t)c * 32 * K);
    }
    CPC();
#pragma unroll
    for (int c = 0; c < 4; c++) {
        CPA(sA[1][c], Ag + (size_t)c * 32 * K + 32);
        CPA(sB[1][c], Bg + (size_t)c * 32 * K + 32);
    }
    CPC();

    for (int kt = 0; kt < KT; kt++) {
        if (kt + 1 < KT) { CPW1(); } else { CPW0(); }
        __syncthreads();
        if (kt + 2 < KT) {
            const int st = (kt + 2) % 3;
            const int ko = (kt + 2) * 32;
#pragma unroll
            for (int c = 0; c < 4; c++) {
                CPA(sA[st][c], Ag + (size_t)c * 32 * K + ko);
                CPA(sB[st][c], Bg + (size_t)c * 32 * K + ko);
            }
            CPC();
        }
        const int buf = kt % 3;
        const uint32_t abase = smemA0 + (uint32_t)buf * (GSTAGE * 4);
        const uint32_t bbase = smemB0 + (uint32_t)buf * (GSTAGE * 4);

#pragma unroll
        for (int ks = 0; ks < 4; ks++) {
            const uint32_t kb = (uint32_t)(ks * 2);
            uint32_t a[2][4], bf[4][4];
            LDSM_X4(a[0], abase + (uint32_t)(arow0 * 128) + (((kb + abo) ^ aswz0) << 4));
            LDSM_X4(a[1], abase + (uint32_t)((arow0 + 16) * 128) + (((kb + abo) ^ aswz1) << 4));
#pragma unroll
            for (int g = 0; g < 4; g++)
                LDSM_X4(bf[g], bbase + browoff[g] + (((kb + bbo) ^ bswz[g]) << 4));
#pragma unroll
            for (int mt = 0; mt < 2; mt++)
#pragma unroll
                for (int nt = 0; nt < 8; nt++)
                    MMA_TF32_2(acc[mt][nt], a[mt],
                               bf[nt >> 1][(nt & 1) * 2], bf[nt >> 1][(nt & 1) * 2 + 1]);
        }
    }

#pragma unroll
    for (int mt = 0; mt < 2; mt++) {
        const int row = m0 + wm + mt * 16 + r;
#pragma unroll
        for (int nt = 0; nt < 8; nt++) {
            const int col = n0 + wn + nt * 8 + cq * 2;
            const float2 bv = *(const float2*)(bias + col);
            float o0 = acc[mt][nt][0] + bv.x;
            float o1 = acc[mt][nt][1] + bv.y;
            float o2 = acc[mt][nt][2] + bv.x;
            float o3 = acc[mt][nt][3] + bv.y;
            if (OP == 1) {
                o0 = tf32r(0.5f * o0 * (1.0f + erff(o0 * 0.7071067811865475f)));
                o1 = tf32r(0.5f * o1 * (1.0f + erff(o1 * 0.7071067811865475f)));
                o2 = tf32r(0.5f * o2 * (1.0f + erff(o2 * 0.7071067811865475f)));
                o3 = tf32r(0.5f * o3 * (1.0f + erff(o3 * 0.7071067811865475f)));
            }
            if (OP == 2) {
                const float2 r0 = *(const float2*)(res + (size_t)row * N + col);
                const float2 r1 = *(const float2*)(res + (size_t)(row + 8) * N + col);
                o0 += r0.x; o1 += r0.y; o2 += r1.x; o3 += r1.y;
            }
            *(float2*)(C + (size_t)row * N + col) = make_float2(o0, o1);
            *(float2*)(C + (size_t)(row + 8) * N + col) = make_float2(o2, o3);
        }
    }
}

// ---------------- LayerNorm: one warp per row ----------------
__global__ void ln_warp_kernel(const float* __restrict__ x, const float* __restrict__ g,
                               const float* __restrict__ bt, float* __restrict__ y,
                               long in_row_stride, int nrows)
{
    const int row = blockIdx.x * 8 + (threadIdx.x >> 5);
    if (row >= nrows) return;
    const int lane = threadIdx.x & 31;
    const float4* xr = (const float4*)(x + (size_t)row * in_row_stride);
    float4 v[3];
    v[0] = xr[lane]; v[1] = xr[lane + 32]; v[2] = xr[lane + 64];
    float s = 0.f, q = 0.f;
#pragma unroll
    for (int t = 0; t < 3; t++) {
        s += v[t].x + v[t].y + v[t].z + v[t].w;
        q += v[t].x * v[t].x + v[t].y * v[t].y + v[t].z * v[t].z + v[t].w * v[t].w;
    }
#pragma unroll
    for (int o = 16; o; o >>= 1) {
        s += __shfl_xor_sync(0xffffffffu, s, o);
        q += __shfl_xor_sync(0xffffffffu, q, o);
    }
    const float mean = s * (1.0f / DD);
    const float rstd = rsqrtf(q * (1.0f / DD) - mean * mean + 1e-5f);
    const float4* gp = (const float4*)g;
    const float4* bp = (const float4*)bt;
    float4* yr = (float4*)(y + (size_t)row * DD);
#pragma unroll
    for (int t = 0; t < 3; t++) {
        float4 gv = gp[lane + 32 * t], bv = bp[lane + 32 * t];
        float4 o;
        o.x = tf32r((v[t].x - mean) * rstd * gv.x + bv.x);
        o.y = tf32r((v[t].y - mean) * rstd * gv.y + bv.y);
        o.z = tf32r((v[t].z - mean) * rstd * gv.z + bv.z);
        o.w = tf32r((v[t].w - mean) * rstd * gv.w + bv.w);
        yr[lane + 32 * t] = o;
    }
}

// ---------------- prep: split K hi/lo and V^T hi/lo into global scratch ----------------
__global__ void __launch_bounds__(256) prep_kv(const float* __restrict__ qkv,
                                               float* __restrict__ ghi, float* __restrict__ glo,
                                               float* __restrict__ gvhi, float* __restrict__ gvlo)
{
    __shared__ float tile[32][68];
    const int bh = blockIdx.x;
    const int b = bh / HEADS, h = bh - b * HEADS;
    const float* base = qkv + (size_t)b * SS * (3 * DD) + h * HD;
    const int tid = threadIdx.x;

    // K rows: [SSP][64], zero-padded
    float* khi = ghi + (size_t)bh * SSP * HD;
    float* klo = glo + (size_t)bh * SSP * HD;
    for (int idx = tid; idx < SSP * 16; idx += 256) {
        int j = idx >> 4, d4 = (idx & 15) * 4;
        float4 v = make_float4(0.f, 0.f, 0.f, 0.f);
        if (j < SS) v = *(const float4*)(base + (size_t)j * (3 * DD) + DD + d4);
        float4 hi, lo;
        split_f(v.x, hi.x, lo.x); split_f(v.y, hi.y, lo.y);
        split_f(v.z, hi.z, lo.z); split_f(v.w, hi.w, lo.w);
        *(float4*)(khi + j * HD + d4) = hi;
        *(float4*)(klo + j * HD + d4) = lo;
    }

    // V transposed: [64][SSP], zero-padded (SSP = 7*32, so all writes in-bounds)
    float* vhi = gvhi + (size_t)bh * HD * SSP;
    float* vlo = gvlo + (size_t)bh * HD * SSP;
    for (int jc = 0; jc < 7; jc++) {
        const int jb = jc * 32;
        __syncthreads();
        for (int idx = tid; idx < 32 * 16; idx += 256) {
            int jj = idx >> 4, d4 = (idx & 15) * 4;
            int j = jb + jj;
            float4 v = make_float4(0.f, 0.f, 0.f, 0.f);
            if (j < SS) v = *(const float4*)(base + (size_t)j * (3 * DD) + 2 * DD + d4);
            *(float4*)&tile[jj][d4] = v;
        }
        __syncthreads();
        for (int idx = tid; idx < 64 * 8; idx += 256) {
            int d = idx >> 3, j4 = (idx & 7) * 4;
            float4 hv, lv;
            split_f(tile[j4 + 0][d], hv.x, lv.x);
            split_f(tile[j4 + 1][d], hv.y, lv.y);
            split_f(tile[j4 + 2][d], hv.z, lv.z);
            split_f(tile[j4 + 3][d], hv.w, lv.w);
            *(float4*)(vhi + (size_t)d * SSP + jb + j4) = hv;
            *(float4*)(vlo + (size_t)d * SSP + jb + j4) = lv;
        }
    }
}

// ---------------- fused flash attention: pre-split K/V, ldmatrix B, chunk=32 ----------------
// smem: Q[128][68] + P[128][36] + Khi[32][68] + Klo[32][68] + Vthi[64][36] + Vtlo[64][36]
// = 89088 B -> 2 blocks/SM
#define FA_SMEM ((128*68 + 128*36 + 2*32*68 + 2*64*36) * 4)

__global__ void __launch_bounds__(256, 2) flash_attn(
    const float* __restrict__ qkv,
    const float* __restrict__ ghi, const float* __restrict__ glo,
    const float* __restrict__ gvhi, const float* __restrict__ gvlo,
    float* __restrict__ ctx)
{
    extern __shared__ float sm[];
    float (*Qs)[68]   = (float(*)[68])sm;            // 128 x 68
    float (*Ps)[36]   = (float(*)[36])(sm + 128 * 68);
    float (*Khi)[68]  = (float(*)[68])(sm + 128 * 68 + 128 * 36);
    float (*Klo)[68]  = Khi + 32;
    float (*Vthi)[36] = (float(*)[36])(sm + 128 * 68 + 128 * 36 + 2 * 32 * 68);
    float (*Vtlo)[36] = Vthi + 64;

    const int bh = blockIdx.y;
    const int b = bh / HEADS, h = bh - b * HEADS;
    const int i0 = blockIdx.x * 128;
    const float* base = qkv + (size_t)b * SS * (3 * DD) + h * HD;
    const float* khi = ghi + (size_t)bh * SSP * HD;
    const float* klo = glo + (size_t)bh * SSP * HD;
    const float* vhi = gvhi + (size_t)bh * HD * SSP;
    const float* vlo = gvlo + (size_t)bh * HD * SSP;

    const int tid = threadIdx.x;
    const int lane = tid & 31, warp = tid >> 5;
    const int wm = warp * 16;
    const int r = lane >> 2, cq = lane & 3;
    const bool wactive = (i0 + wm) < SS;

    // ldmatrix lane mapping (R9-validated pattern, strides conflict-free without XOR)
    const int lm = lane >> 3;
    const int rit = lane & 7;
    const int bnt = lm >> 1;
    const int bbo = lm & 1;
    uint32_t growk[2], growv[4];
#pragma unroll
    for (int g = 0; g < 2; g++)
        growk[g] = (uint32_t)(((2 * g + bnt) * 8 + rit) * 272);    // 68 floats * 4B
#pragma unroll
    for (int g = 0; g < 4; g++)
        growv[g] = (uint32_t)(((2 * g + bnt) * 8 + rit) * 144);    // 36 floats * 4B
    const uint32_t khi0 = smem_u32(Khi), klo0 = smem_u32(Klo);
    const uint32_t vhi0 = smem_u32(Vthi), vlo0 = smem_u32(Vtlo);

    // load Q (128 x 64), scaled, fp32
    for (int idx = tid; idx < 128 * 16; idx += 256) {
        int ii = idx >> 4, d4 = (idx & 15) * 4;
        int i = i0 + ii;
        float4 v = make_float4(0.f, 0.f, 0.f, 0.f);
        if (i < SS) v = *(const float4*)(base + (size_t)i * (3 * DD) + d4);
        Qs[ii][d4 + 0] = v.x * 0.125f;
        Qs[ii][d4 + 1] = v.y * 0.125f;
        Qs[ii][d4 + 2] = v.z * 0.125f;
        Qs[ii][d4 + 3] = v.w * 0.125f;
    }

    float o[8][4];
#pragma unroll
    for (int nt = 0; nt < 8; nt++)
#pragma unroll
        for (int i = 0; i < 4; i++) o[nt][i] = 0.f;
    float m0 = -1e30f, m1 = -1e30f, l0 = 0.f, l1 = 0.f;

    for (int jc = 0; jc < 7; jc++) {
        const int jb = jc * 32;
        const int ntmax = (jc < 6) ? 4 : 1;      // last chunk: cols 192..196
        __syncthreads();                          // prev chunk reads done

        // load pre-split K chunk (32 x 64 hi + lo)
        for (int idx = tid; idx < 32 * 16; idx += 256) {
            int jj = idx >> 4, d4 = (idx & 15) * 4;
            *(float4*)&Khi[jj][d4] = *(const float4*)(khi + (size_t)(jb + jj) * HD + d4);
            *(float4*)&Klo[jj][d4] = *(const float4*)(klo + (size_t)(jb + jj) * HD + d4);
        }
        // load pre-split V^T chunk (64 x 32 hi + lo)
        for (int idx = tid; idx < 64 * 8; idx += 256) {
            int d = idx >> 3, j4 = (idx & 7) * 4;
            *(float4*)&Vthi[d][j4] = *(const float4*)(vhi + (size_t)d * SSP + jb + j4);
            *(float4*)&Vtlo[d][j4] = *(const float4*)(vlo + (size_t)d * SSP + jb + j4);
        }
        __syncthreads();

        if (wactive) {
            // ---- S = Q K^T (16 x 32 per warp) ----
            float s[4][4];
#pragma unroll
            for (int nt = 0; nt < 4; nt++)
#pragma unroll
                for (int i = 0; i < 4; i++) s[nt][i] = 0.f;

            const int gmaxS = (ntmax + 1) >> 1;  // 2 or 1
#pragma unroll
            for (int k0 = 0; k0 < 64; k0 += 8) {
                const uint32_t kb16 = (uint32_t)(((k0 >> 2) + bbo) << 4);
                uint32_t ahi[4], alo[4];
                split_u(Qs[wm + r][k0 + cq],         ahi[0], alo[0]);
                split_u(Qs[wm + r + 8][k0 + cq],     ahi[1], alo[1]);
                split_u(Qs[wm + r][k0 + cq + 4],     ahi[2], alo[2]);
                split_u(Qs[wm + r + 8][k0 + cq + 4], ahi[3], alo[3]);
                uint32_t bfh[2][4], bfl[2][4];
                for (int g = 0; g < gmaxS; g++) {
                    LDSM_X4(bfh[g], khi0 + growk[g] + kb16);
                    LDSM_X4(bfl[g], klo0 + growk[g] + kb16);
                }
                for (int nt = 0; nt < ntmax; nt++) {
                    const int g = nt >> 1, sel = (nt & 1) * 2;
                    MMA_TF32_2(s[nt], ahi, bfh[g][sel], bfh[g][sel + 1]);
                    MMA_TF32_2(s[nt], ahi, bfl[g][sel], bfl[g][sel + 1]);
                    MMA_TF32_2(s[nt], alo, bfh[g][sel], bfh[g][sel + 1]);
                }
            }

            // ---- mask, rowwise max (quad), online softmax ----
            float mx0 = -1e30f, mx1 = -1e30f;
            for (int nt = 0; nt < ntmax; nt++) {
                int col = jb + nt * 8 + cq * 2;
                if (col >= SS)     { s[nt][0] = s[nt][2] = -1e30f; }
                if (col + 1 >= SS) { s[nt][1] = s[nt][3] = -1e30f; }
                mx0 = fmaxf(mx0, fmaxf(s[nt][0], s[nt][1]));
                mx1 = fmaxf(mx1, fmaxf(s[nt][2], s[nt][3]));
            }
            mx0 = fmaxf(mx0, __shfl_xor_sync(0xffffffffu, mx0, 1));
            mx0 = fmaxf(mx0, __shfl_xor_sync(0xffffffffu, mx0, 2));
            mx1 = fmaxf(mx1, __shfl_xor_sync(0xffffffffu, mx1, 1));
            mx1 = fmaxf(mx1, __shfl_xor_sync(0xffffffffu, mx1, 2));

            const float mn0 = fmaxf(m0, mx0), mn1 = fmaxf(m1, mx1);
            const float sc0 = __expf(m0 - mn0), sc1 = __expf(m1 - mn1);
            float sum0 = 0.f, sum1 = 0.f;
            for (int nt = 0; nt < ntmax; nt++) {
                int cc = nt * 8 + cq * 2;
                float p0 = __expf(s[nt][0] - mn0);
                float p1 = __expf(s[nt][1] - mn0);
                float p2 = __expf(s[nt][2] - mn1);
                float p3 = __expf(s[nt][3] - mn1);
                sum0 += p0 + p1;
                sum1 += p2 + p3;
                Ps[wm + r][cc] = p0;     Ps[wm + r][cc + 1] = p1;
                Ps[wm + r + 8][cc] = p2; Ps[wm + r + 8][cc + 1] = p3;
            }
            sum0 += __shfl_xor_sync(0xffffffffu, sum0, 1);
            sum0 += __shfl_xor_sync(0xffffffffu, sum0, 2);
            sum1 += __shfl_xor_sync(0xffffffffu, sum1, 1);
            sum1 += __shfl_xor_sync(0xffffffffu, sum1, 2);
            l0 = l0 * sc0 + sum0;
            l1 = l1 * sc1 + sum1;
            m0 = mn0; m1 = mn1;
#pragma unroll
            for (int nt = 0; nt < 8; nt++) {
                o[nt][0] *= sc0; o[nt][1] *= sc0;
                o[nt][2] *= sc1; o[nt][3] *= sc1;
            }
            __syncwarp();

            // ---- O += P V (k = chunk cols) ----
            const int kmax = ntmax * 8;
            for (int k0 = 0; k0 < kmax; k0 += 8) {
                const uint32_t kb16 = (uint32_t)(((k0 >> 2) + bbo) << 4);
                uint32_t ahi[4], alo[4];
                split_u(Ps[wm + r][k0 + cq],         ahi[0], alo[0]);
                split_u(Ps[wm + r + 8][k0 + cq],     ahi[1], alo[1]);
                split_u(Ps[wm + r][k0 + cq + 4],     ahi[2], alo[2]);
                split_u(Ps[wm + r + 8][k0 + cq + 4], ahi[3], alo[3]);
                uint32_t bfh[4][4], bfl[4][4];
#pragma unroll
                for (int g = 0; g < 4; g++) {
                    LDSM_X4(bfh[g], vhi0 + growv[g] + kb16);
                    LDSM_X4(bfl[g], vlo0 + growv[g] + kb16);
                }
#pragma unroll
                for (int nt = 0; nt < 8; nt++) {
                    const int g = nt >> 1, sel = (nt & 1) * 2;
                    MMA_TF32_2(o[nt], ahi, bfh[g][sel], bfh[g][sel + 1]);
                    MMA_TF32_2(o[nt], ahi, bfl[g][sel], bfl[g][sel + 1]);
                    MMA_TF32_2(o[nt], alo, bfh[g][sel], bfh[g][sel + 1]);
                }
            }
        }
    }

    if (wactive) {
        const float inv0 = 1.0f / l0, inv1 = 1.0f / l1;
        const int row0 = i0 + wm + r, row1 = row0 + 8;
#pragma unroll
        for (int nt = 0; nt < 8; nt++) {
            const int col = h * HD + nt * 8 + cq * 2;
            if (row0 < SS) {
                float2 ov = make_float2(tf32r(o[nt][0] * inv0), tf32r(o[nt][1] * inv0));
                *(float2*)&ctx[((size_t)b * SS + row0) * DD + col] = ov;
            }
            if (row1 < SS) {
                float2 ov = make_float2(tf32r(o[nt][2] * inv1), tf32r(o[nt][3] * inv1));
                *(float2*)&ctx[((size_t)b * SS + row1) * DD + col] = ov;
            }
        }
    }
}

// ---------------- classifier head ----------------
__global__ void head_kernel(const float* __restrict__ cls, const float* __restrict__ hw,
                            float* __restrict__ out)
{
    __shared__ float s[DD];
    int b = blockIdx.x;
    for (int k = threadIdx.x; k < DD; k += blockDim.x) s[k] = cls[(size_t)b * DD + k];
    __syncthreads();
    int c = threadIdx.x;
    if (c < NCLS) {
        const float* w = hw + (size_t)c * DD;
        float acc = 0.f;
#pragma unroll 8
        for (int k = 0; k < DD; k++) acc += s[k] * w[k];
        out[(size_t)b * NCLS + c] = acc;
    }
}

// ---------------- launch ----------------
extern "C" void kernel_launch(void* const* d_in, const int* in_sizes, int n_in,
                              void* d_out, int out_size) {
    const float* x         = (const float*)d_in[0];
    const float* patch_w   = (const float*)d_in[1];
    const float* patch_b   = (const float*)d_in[2];
    const float* cls_token = (const float*)d_in[3];
    const float* pos_embed = (const float*)d_in[4];
    const float* ln1_g     = (const float*)d_in[5];
    const float* ln1_b     = (const float*)d_in[6];
    const float* qkv_w     = (const float*)d_in[7];
    const float* qkv_b     = (const float*)d_in[8];
    const float* out_w     = (const float*)d_in[9];
    const float* out_b     = (const float*)d_in[10];
    const float* ln2_g     = (const float*)d_in[11];
    const float* ln2_b     = (const float*)d_in[12];
    const float* fc1_w     = (const float*)d_in[13];
    const float* fc1_b     = (const float*)d_in[14];
    const float* fc2_w     = (const float*)d_in[15];
    const float* fc2_b     = (const float*)d_in[16];
    const float* lnf_g     = (const float*)d_in[17];
    const float* lnf_b     = (const float*)d_in[18];
    const float* head_w    = (const float*)d_in[19];
    float* out = (float*)d_out;

    float *patches, *tok, *h, *xn, *qkv, *ctx, *hid, *cls, *w;
    float *khi, *klo, *vthi, *vtlo;
    cudaGetSymbolAddress((void**)&patches, g_patches);
    cudaGetSymbolAddress((void**)&tok, g_tok);
    cudaGetSymbolAddress((void**)&h, g_h);
    cudaGetSymbolAddress((void**)&xn, g_xn);
    cudaGetSymbolAddress((void**)&qkv, g_qkv);
    cudaGetSymbolAddress((void**)&ctx, g_ctx);
    cudaGetSymbolAddress((void**)&hid, g_hid);
    cudaGetSymbolAddress((void**)&cls, g_cls);
    cudaGetSymbolAddress((void**)&w, g_w);
    cudaGetSymbolAddress((void**)&khi, g_khi);
    cudaGetSymbolAddress((void**)&klo, g_klo);
    cudaGetSymbolAddress((void**)&vthi, g_vthi);
    cudaGetSymbolAddress((void**)&vtlo, g_vtlo);

    cudaFuncSetAttribute(gemm_tf32<0>, cudaFuncAttributeMaxDynamicSharedMemorySize, GEMM_SMEM);
    cudaFuncSetAttribute(gemm_tf32<1>, cudaFuncAttributeMaxDynamicSharedMemorySize, GEMM_SMEM);
    cudaFuncSetAttribute(gemm_tf32<2>, cudaFuncAttributeMaxDynamicSharedMemorySize, GEMM_SMEM);
    cudaFuncSetAttribute(flash_attn, cudaFuncAttributeMaxDynamicSharedMemorySize, FA_SMEM);

    // 0,1: weight rounding; 2: patchify; 3: patch GEMM (profiled index)
    round_w_a<<<(W_FC1 / 4 + 255) / 256, 256>>>(patch_w, qkv_w, out_w, w);
    round_w_b<<<((W_TOTAL - W_FC1) / 4 + 255) / 256, 256>>>(fc1_w, fc2_w, w);
    patchify_kernel<<<(PTOK * PATCH_DIM + 255) / 256, 256>>>(x, patches);
    gemm_tf32<0><<<dim3(DD / 128, PTOK / 128), 256, GEMM_SMEM>>>(
        patches, w + W_PATCH, patch_b, nullptr, tok, PTOK, DD, PATCH_DIM);
    assemble_kernel<<<(TOK * DD + 255) / 256, 256>>>(tok, cls_token, pos_embed, h);

    for (int i = 0; i < DEPTH; i++) {
        ln_warp_kernel<<<(TOK + 7) / 8, 256>>>(h, ln1_g + i * DD, ln1_b + i * DD, xn, DD, TOK);
        gemm_tf32<0><<<dim3(3 * DD / 128, TOK / 128), 256, GEMM_SMEM>>>(
            xn, w + W_QKV + (size_t)i * 3 * DD * DD, qkv_b + (size_t)i * 3 * DD,
            nullptr, qkv, TOK, 3 * DD, DD);
        prep_kv<<<BH, 256>>>(qkv, khi, klo, vthi, vtlo);
        flash_attn<<<dim3(2, BH), 256, FA_SMEM>>>(qkv, khi, klo, vthi, vtlo, ctx);
        gemm_tf32<2><<<dim3(DD / 128, TOK / 128), 256, GEMM_SMEM>>>(
            ctx, w + W_OUT + (size_t)i * DD * DD, out_b + (size_t)i * DD, h, h, TOK, DD, DD);
        ln_warp_kernel<<<(TOK + 7) / 8, 256>>>(h, ln2_g + i * DD, ln2_b + i * DD, xn, DD, TOK);
        gemm_tf32<1><<<dim3(HID / 128, TOK / 128), 256, GEMM_SMEM>>>(
            xn, w + W_FC1 + (size_t)i * HID * DD, fc1_b + (size_t)i * HID,
            nullptr, hid, TOK, HID, DD);
        gemm_tf32<2><<<dim3(DD / 128, TOK / 128), 256, GEMM_SMEM>>>(
            hid, w + W_FC2 + (size_t)i * DD * HID, fc2_b + (size_t)i * DD, h, h, TOK, DD, HID);
    }

    ln_warp_kernel<<<(BB + 7) / 8, 256>>>(h, lnf_g, lnf_b, cls, (long)SS * DD, BB);
    head_kernel<<<BB, 128>>>(cls, head_w, out);
}

// round 14
// speedup vs baseline: 1.1550x; 1.1550x over previous
#include <cuda_runtime.h>
#include <math.h>
#include <stdint.h>

// ---------------- problem constants ----------------
#define BB 128
#define CC 3
#define IMG 224
#define PP 16
#define HP 14
#define NP 196
#define SS 197
#define DD 384
#define HEADS 6
#define HD 64
#define DEPTH 12
#define HID 1536
#define NCLS 100
#define PATCH_DIM 768
#define TOK (BB*SS)    // 25216
#define PTOK (BB*NP)   // 25088
#define BH (BB*HEADS)  // 768

// ---------------- scratch ----------------
__device__ float g_patches[PTOK * PATCH_DIM];
__device__ float g_tok[PTOK * DD];
__device__ float g_h[TOK * DD];
__device__ float g_xn[TOK * DD];
__device__ float g_qkv[TOK * 3 * DD];
__device__ float g_ctx[TOK * DD];
__device__ float g_hid[TOK * HID];
__device__ float g_cls[BB * DD];
// tf32-rounded weights (offsets in floats)
#define W_PATCH 0
#define W_QKV   294912
#define W_OUT   5603328
#define W_FC1   7372800
#define W_FC2   14450688
#define W_TOTAL 21528576
__device__ float g_w[W_TOTAL];

// ---------------- helpers ----------------
__device__ __forceinline__ float tf32r(float x) {
    uint32_t u;
    asm("cvt.rna.tf32.f32 %0, %1;" : "=r"(u) : "f"(x));
    return __uint_as_float(u);
}
__device__ __forceinline__ void split_u(float x, uint32_t& hi, uint32_t& lo) {
    float h = tf32r(x);
    hi = __float_as_uint(h);
    lo = __float_as_uint(tf32r(x - h));
}
__device__ __forceinline__ uint32_t smem_u32(const void* p) {
    return (uint32_t)__cvta_generic_to_shared(p);
}
#define CPA(dst, src) asm volatile("cp.async.cg.shared.global [%0], [%1], 16;" :: "r"(dst), "l"(src))
#define CPC() asm volatile("cp.async.commit_group;")
#define CPW0() asm volatile("cp.async.wait_group 0;")
#define CPW1() asm volatile("cp.async.wait_group 1;")
#define MMA_TF32(d, a, b) asm volatile( \
    "mma.sync.aligned.m16n8k8.row.col.f32.tf32.tf32.f32 " \
    "{%0,%1,%2,%3},{%4,%5,%6,%7},{%8,%9},{%0,%1,%2,%3};" \
    : "+f"(d[0]), "+f"(d[1]), "+f"(d[2]), "+f"(d[3]) \
    : "r"(a[0]), "r"(a[1]), "r"(a[2]), "r"(a[3]), "r"(b[0]), "r"(b[1]))
#define MMA_TF32_2(d, a, b0v, b1v) asm volatile( \
    "mma.sync.aligned.m16n8k8.row.col.f32.tf32.tf32.f32 " \
    "{%0,%1,%2,%3},{%4,%5,%6,%7},{%8,%9},{%0,%1,%2,%3};" \
    : "+f"(d[0]), "+f"(d[1]), "+f"(d[2]), "+f"(d[3]) \
    : "r"(a[0]), "r"(a[1]), "r"(a[2]), "r"(a[3]), "r"(b0v), "r"(b1v))
#define LDSM_X4(f, addr) asm volatile( \
    "ldmatrix.sync.aligned.m8n8.x4.shared.b16 {%0,%1,%2,%3}, [%4];" \
    : "=r"((f)[0]), "=r"((f)[1]), "=r"((f)[2]), "=r"((f)[3]) : "r"(addr))

// ---------------- weight rounding (2 launches for profiler indexing) ----------------
__global__ void round_w_a(const float* __restrict__ pw, const float* __restrict__ qw,
                          const float* __restrict__ ow, float* __restrict__ w) {
    int i = blockIdx.x * blockDim.x + threadIdx.x;
    if (i >= W_FC1 / 4) return;
    int f = i * 4;
    const float* src; int off;
    if (f < W_QKV)      { src = pw; off = f - W_PATCH; }
    else if (f < W_OUT) { src = qw; off = f - W_QKV; }
    else                { src = ow; off = f - W_OUT; }
    float4 v = *(const float4*)(src + off);
    v.x = tf32r(v.x); v.y = tf32r(v.y); v.z = tf32r(v.z); v.w = tf32r(v.w);
    ((float4*)w)[i] = v;
}
__global__ void round_w_b(const float* __restrict__ f1, const float* __restrict__ f2,
                          float* __restrict__ w) {
    int i = blockIdx.x * blockDim.x + threadIdx.x;
    if (i >= (W_TOTAL - W_FC1) / 4) return;
    int f = W_FC1 + i * 4;
    const float* src; int off;
    if (f < W_FC2) { src = f1; off = f - W_FC1; }
    else           { src = f2; off = f - W_FC2; }
    float4 v = *(const float4*)(src + off);
    v.x = tf32r(v.x); v.y = tf32r(v.y); v.z = tf32r(v.z); v.w = tf32r(v.w);
    ((float4*)(w + W_FC1))[i] = v;
}

// ---------------- patchify (+tf32 round) ----------------
__global__ void patchify_kernel(const float* __restrict__ x, float* __restrict__ patches) {
    int idx = blockIdx.x * blockDim.x + threadIdx.x;
    if (idx >= PTOK * PATCH_DIM) return;
    int t = idx / PATCH_DIM;
    int k = idx - t * PATCH_DIM;
    int b = t / NP;
    int n = t - b * NP;
    int ph = n / HP, pw = n - ph * HP;
    int c = k >> 8;
    int py = (k >> 4) & 15;
    int px = k & 15;
    patches[idx] = tf32r(x[(((size_t)b * CC + c) * IMG + (ph * PP + py)) * IMG + (pw * PP + px)]);
}

// ---------------- assemble h = [cls; tok] + pos ----------------
__global__ void assemble_kernel(const float* __restrict__ tok, const float* __restrict__ cls_token,
                                const float* __restrict__ pos, float* __restrict__ h) {
    int idx = blockIdx.x * blockDim.x + threadIdx.x;
    if (idx >= TOK * DD) return;
    int row = idx / DD;
    int d = idx - row * DD;
    int b = row / SS;
    int s = row - b * SS;
    float v = (s == 0) ? cls_token[d] : tok[((size_t)b * NP + (s - 1)) * DD + d];
    h[idx] = v + pos[s * DD + d];
}

// ---------------- tf32 NT GEMM: swizzled smem, 3-stage cp.async, ldmatrix fragments ----------------
#define GSTAGE 4096
#define GEMM_SMEM (3 * 2 * GSTAGE * 4)      // 98304 B

template <int OP>
__global__ void __launch_bounds__(256, 2) gemm_tf32(
    const float* __restrict__ A, const float* __restrict__ Bw,
    const float* __restrict__ bias, const float* __restrict__ res,
    float* __restrict__ C, int M, int N, int K)
{
    extern __shared__ float gsm[];
    float* As = gsm;
    float* Bs = gsm + 3 * GSTAGE;

    const int tid = threadIdx.x;
    const int lane = tid & 31, warp = tid >> 5;
    const int wm = (warp >> 1) * 32;
    const int wn = (warp & 1) * 64;
    const int r = lane >> 2, cq = lane & 3;
    const int m0 = blockIdx.y * 128, n0 = blockIdx.x * 128;

    const int lr = tid >> 3;
    const int lc = (tid & 7) * 4;
    const int sw = (lr & 7) * 4;
    const float* Ag = A + (size_t)(m0 + lr) * K + lc;
    const float* Bg = Bw + (size_t)(n0 + lr) * K + lc;
    uint32_t sA[3][4], sB[3][4];
#pragma unroll
    for (int s = 0; s < 3; s++)
#pragma unroll
        for (int c = 0; c < 4; c++) {
            sA[s][c] = smem_u32(As + (size_t)s * GSTAGE + (lr + c * 32) * 32 + (lc ^ sw));
            sB[s][c] = smem_u32(Bs + (size_t)s * GSTAGE + (lr + c * 32) * 32 + (lc ^ sw));
        }

    const int lm = lane >> 3;
    const int rit = lane & 7;
    const int arow0 = wm + ((lm & 1) * 8) + rit;
    const int abo = lm >> 1;
    const uint32_t aswz0 = (uint32_t)(arow0 & 7);
    const uint32_t aswz1 = (uint32_t)((arow0 + 16) & 7);
    const int bnt = lm >> 1;
    const int bbo = lm & 1;
    uint32_t browoff[4], bswz[4];
#pragma unroll
    for (int g = 0; g < 4; g++) {
        int brow = wn + (2 * g + bnt) * 8 + rit;
        browoff[g] = (uint32_t)(brow * 128);
        bswz[g] = (uint32_t)(brow & 7);
    }
    const uint32_t smemA0 = smem_u32(As);
    const uint32_t smemB0 = smem_u32(Bs);

    float acc[2][8][4];
#pragma unroll
    for (int mt = 0; mt < 2; mt++)
#pragma unroll
        for (int nt = 0; nt < 8; nt++)
#pragma unroll
            for (int i = 0; i < 4; i++) acc[mt][nt][i] = 0.f;

    const int KT = K / 32;
#pragma unroll
    for (int c = 0; c < 4; c++) {
        CPA(sA[0][c], Ag + (size_t)c * 32 * K);
        CPA(sB[0][c], Bg + (size_t)c * 32 * K);
    }
    CPC();
#pragma unroll
    for (int c = 0; c < 4; c++) {
        CPA(sA[1][c], Ag + (size_t)c * 32 * K + 32);
        CPA(sB[1][c], Bg + (size_t)c * 32 * K + 32);
    }
    CPC();

    for (int kt = 0; kt < KT; kt++) {
        if (kt + 1 < KT) { CPW1(); } else { CPW0(); }
        __syncthreads();
        if (kt + 2 < KT) {
            const int st = (kt + 2) % 3;
            const int ko = (kt + 2) * 32;
#pragma unroll
            for (int c = 0; c < 4; c++) {
                CPA(sA[st][c], Ag + (size_t)c * 32 * K + ko);
                CPA(sB[st][c], Bg + (size_t)c * 32 * K + ko);
            }
            CPC();
        }
        const int buf = kt % 3;
        const uint32_t abase = smemA0 + (uint32_t)buf * (GSTAGE * 4);
        const uint32_t bbase = smemB0 + (uint32_t)buf * (GSTAGE * 4);

#pragma unroll
        for (int ks = 0; ks < 4; ks++) {
            const uint32_t kb = (uint32_t)(ks * 2);
            uint32_t a[2][4], bf[4][4];
            LDSM_X4(a[0], abase + (uint32_t)(arow0 * 128) + (((kb + abo) ^ aswz0) << 4));
            LDSM_X4(a[1], abase + (uint32_t)((arow0 + 16) * 128) + (((kb + abo) ^ aswz1) << 4));
#pragma unroll
            for (int g = 0; g < 4; g++)
                LDSM_X4(bf[g], bbase + browoff[g] + (((kb + bbo) ^ bswz[g]) << 4));
#pragma unroll
            for (int mt = 0; mt < 2; mt++)
#pragma unroll
                for (int nt = 0; nt < 8; nt++)
                    MMA_TF32_2(acc[mt][nt], a[mt],
                               bf[nt >> 1][(nt & 1) * 2], bf[nt >> 1][(nt & 1) * 2 + 1]);
        }
    }

#pragma unroll
    for (int mt = 0; mt < 2; mt++) {
        const int row = m0 + wm + mt * 16 + r;
#pragma unroll
        for (int nt = 0; nt < 8; nt++) {
            const int col = n0 + wn + nt * 8 + cq * 2;
            const float2 bv = *(const float2*)(bias + col);
            float o0 = acc[mt][nt][0] + bv.x;
            float o1 = acc[mt][nt][1] + bv.y;
            float o2 = acc[mt][nt][2] + bv.x;
            float o3 = acc[mt][nt][3] + bv.y;
            if (OP == 1) {
                o0 = tf32r(0.5f * o0 * (1.0f + erff(o0 * 0.7071067811865475f)));
                o1 = tf32r(0.5f * o1 * (1.0f + erff(o1 * 0.7071067811865475f)));
                o2 = tf32r(0.5f * o2 * (1.0f + erff(o2 * 0.7071067811865475f)));
                o3 = tf32r(0.5f * o3 * (1.0f + erff(o3 * 0.7071067811865475f)));
            }
            if (OP == 2) {
                const float2 r0 = *(const float2*)(res + (size_t)row * N + col);
                const float2 r1 = *(const float2*)(res + (size_t)(row + 8) * N + col);
                o0 += r0.x; o1 += r0.y; o2 += r1.x; o3 += r1.y;
            }
            *(float2*)(C + (size_t)row * N + col) = make_float2(o0, o1);
            *(float2*)(C + (size_t)(row + 8) * N + col) = make_float2(o2, o3);
        }
    }
}

// ---------------- LayerNorm: one warp per row ----------------
__global__ void ln_warp_kernel(const float* __restrict__ x, const float* __restrict__ g,
                               const float* __restrict__ bt, float* __restrict__ y,
                               long in_row_stride, int nrows)
{
    const int row = blockIdx.x * 8 + (threadIdx.x >> 5);
    if (row >= nrows) return;
    const int lane = threadIdx.x & 31;
    const float4* xr = (const float4*)(x + (size_t)row * in_row_stride);
    float4 v[3];
    v[0] = xr[lane]; v[1] = xr[lane + 32]; v[2] = xr[lane + 64];
    float s = 0.f, q = 0.f;
#pragma unroll
    for (int t = 0; t < 3; t++) {
        s += v[t].x + v[t].y + v[t].z + v[t].w;
        q += v[t].x * v[t].x + v[t].y * v[t].y + v[t].z * v[t].z + v[t].w * v[t].w;
    }
#pragma unroll
    for (int o = 16; o; o >>= 1) {
        s += __shfl_xor_sync(0xffffffffu, s, o);
        q += __shfl_xor_sync(0xffffffffu, q, o);
    }
    const float mean = s * (1.0f / DD);
    const float rstd = rsqrtf(q * (1.0f / DD) - mean * mean + 1e-5f);
    const float4* gp = (const float4*)g;
    const float4* bp = (const float4*)bt;
    float4* yr = (float4*)(y + (size_t)row * DD);
#pragma unroll
    for (int t = 0; t < 3; t++) {
        float4 gv = gp[lane + 32 * t], bv = bp[lane + 32 * t];
        float4 o;
        o.x = tf32r((v[t].x - mean) * rstd * gv.x + bv.x);
        o.y = tf32r((v[t].y - mean) * rstd * gv.y + bv.y);
        o.z = tf32r((v[t].z - mean) * rstd * gv.z + bv.z);
        o.w = tf32r((v[t].w - mean) * rstd * gv.w + bv.w);
        yr[lane + 32 * t] = o;
    }
}

// ---------------- fused flash attention (R11 shape), fp32 smem + split-at-use 3xTF32 ----------------
#define FA_SMEM ((128 + 64 + 64 + 128) * 68 * 4)

__global__ void __launch_bounds__(256, 2) flash_attn(const float* __restrict__ qkv,
                                                     float* __restrict__ ctx)
{
    extern __shared__ float sm[];
    float (*Qs)[68] = (float(*)[68])sm;
    float (*Ks)[68] = Qs + 128;
    float (*Vt)[68] = Ks + 64;
    float (*Ps)[68] = Vt + 64;

    const int bh = blockIdx.y;
    const int b = bh / HEADS, h = bh - b * HEADS;
    const int i0 = blockIdx.x * 128;
    const float* base = qkv + (size_t)b * SS * (3 * DD) + h * HD;

    const int tid = threadIdx.x;
    const int lane = tid & 31, warp = tid >> 5;
    const int wm = warp * 16;
    const int r = lane >> 2, cq = lane & 3;
    const bool wactive = (i0 + wm) < SS;

    for (int idx = tid; idx < 128 * 16; idx += 256) {
        int ii = idx >> 4, d4 = (idx & 15) * 4;
        int i = i0 + ii;
        float4 v = make_float4(0.f, 0.f, 0.f, 0.f);
        if (i < SS) v = *(const float4*)(base + (size_t)i * (3 * DD) + d4);
        Qs[ii][d4 + 0] = v.x * 0.125f;
        Qs[ii][d4 + 1] = v.y * 0.125f;
        Qs[ii][d4 + 2] = v.z * 0.125f;
        Qs[ii][d4 + 3] = v.w * 0.125f;
    }

    float o[8][4];
#pragma unroll
    for (int nt = 0; nt < 8; nt++)
#pragma unroll
        for (int i = 0; i < 4; i++) o[nt][i] = 0.f;
    float m0 = -1e30f, m1 = -1e30f, l0 = 0.f, l1 = 0.f;

    for (int jc = 0; jc < 4; jc++) {
        const int jb = jc * 64;
        const int ntmax = (jc < 3) ? 8 : 1;
        __syncthreads();

        for (int idx = tid; idx < 64 * 16; idx += 256) {
            int jj = idx >> 4, d4 = (idx & 15) * 4;
            int j = jb + jj;
            float4 v = make_float4(0.f, 0.f, 0.f, 0.f);
            if (j < SS) v = *(const float4*)(base + (size_t)j * (3 * DD) + DD + d4);
            Ks[jj][d4 + 0] = v.x; Ks[jj][d4 + 1] = v.y;
            Ks[jj][d4 + 2] = v.z; Ks[jj][d4 + 3] = v.w;
        }
        for (int idx = tid; idx < 64 * 16; idx += 256) {
            int jj = idx >> 4, d4 = (idx & 15) * 4;
            int j = jb + jj;
            float4 v = make_float4(0.f, 0.f, 0.f, 0.f);
            if (j < SS) v = *(const float4*)(base + (size_t)j * (3 * DD) + 2 * DD + d4);
            Vt[d4 + 0][jj] = v.x; Vt[d4 + 1][jj] = v.y;
            Vt[d4 + 2][jj] = v.z; Vt[d4 + 3][jj] = v.w;
        }
        __syncthreads();

        if (wactive) {
            float s[8][4];
#pragma unroll
            for (int nt = 0; nt < 8; nt++)
#pragma unroll
                for (int i = 0; i < 4; i++) s[nt][i] = 0.f;

#pragma unroll
            for (int k0 = 0; k0 < 64; k0 += 8) {
                uint32_t ahi[4], alo[4];
                split_u(Qs[wm + r][k0 + cq],         ahi[0], alo[0]);
                split_u(Qs[wm + r + 8][k0 + cq],     ahi[1], alo[1]);
                split_u(Qs[wm + r][k0 + cq + 4],     ahi[2], alo[2]);
                split_u(Qs[wm + r + 8][k0 + cq + 4], ahi[3], alo[3]);
                for (int nt = 0; nt < ntmax; nt++) {
                    uint32_t bhi[2], blo[2];
                    split_u(Ks[nt * 8 + r][k0 + cq],     bhi[0], blo[0]);
                    split_u(Ks[nt * 8 + r][k0 + cq + 4], bhi[1], blo[1]);
                    MMA_TF32(s[nt], ahi, bhi);
                    MMA_TF32(s[nt], ahi, blo);
                    MMA_TF32(s[nt], alo, bhi);
                }
            }

            float mx0 = -1e30f, mx1 = -1e30f;
            for (int nt = 0; nt < ntmax; nt++) {
                int col = jb + nt * 8 + cq * 2;
                if (col >= SS)     { s[nt][0] = s[nt][2] = -1e30f; }
                if (col + 1 >= SS) { s[nt][1] = s[nt][3] = -1e30f; }
                mx0 = fmaxf(mx0, fmaxf(s[nt][0], s[nt][1]));
                mx1 = fmaxf(mx1, fmaxf(s[nt][2], s[nt][3]));
            }
            mx0 = fmaxf(mx0, __shfl_xor_sync(0xffffffffu, mx0, 1));
            mx0 = fmaxf(mx0, __shfl_xor_sync(0xffffffffu, mx0, 2));
            mx1 = fmaxf(mx1, __shfl_xor_sync(0xffffffffu, mx1, 1));
            mx1 = fmaxf(mx1, __shfl_xor_sync(0xffffffffu, mx1, 2));

            const float mn0 = fmaxf(m0, mx0), mn1 = fmaxf(m1, mx1);
            const float sc0 = __expf(m0 - mn0), sc1 = __expf(m1 - mn1);
            float sum0 = 0.f, sum1 = 0.f;
            for (int nt = 0; nt < ntmax; nt++) {
                int cc = nt * 8 + cq * 2;
                float p0 = __expf(s[nt][0] - mn0);
                float p1 = __expf(s[nt][1] - mn0);
                float p2 = __expf(s[nt][2] - mn1);
                float p3 = __expf(s[nt][3] - mn1);
                sum0 += p0 + p1;
                sum1 += p2 + p3;
                *(float2*)&Ps[wm + r][cc]     = make_float2(p0, p1);
                *(float2*)&Ps[wm + r + 8][cc] = make_float2(p2, p3);
            }
            sum0 += __shfl_xor_sync(0xffffffffu, sum0, 1);
            sum0 += __shfl_xor_sync(0xffffffffu, sum0, 2);
            sum1 += __shfl_xor_sync(0xffffffffu, sum1, 1);
            sum1 += __shfl_xor_sync(0xffffffffu, sum1, 2);
            l0 = l0 * sc0 + sum0;
            l1 = l1 * sc1 + sum1;
            m0 = mn0; m1 = mn1;
#pragma unroll
            for (int nt = 0; nt < 8; nt++) {
                o[nt][0] *= sc0; o[nt][1] *= sc0;
                o[nt][2] *= sc1; o[nt][3] *= sc1;
            }
            __syncwarp();

            for (int k0 = 0; k0 < ntmax * 8; k0 += 8) {
                uint32_t ahi[4], alo[4];
                split_u(Ps[wm + r][k0 + cq],         ahi[0], alo[0]);
                split_u(Ps[wm + r + 8][k0 + cq],     ahi[1], alo[1]);
                split_u(Ps[wm + r][k0 + cq + 4],     ahi[2], alo[2]);
                split_u(Ps[wm + r + 8][k0 + cq + 4], ahi[3], alo[3]);
#pragma unroll
                for (int nt = 0; nt < 8; nt++) {
                    uint32_t bhi[2], blo[2];
                    split_u(Vt[nt * 8 + r][k0 + cq],     bhi[0], blo[0]);
                    split_u(Vt[nt * 8 + r][k0 + cq + 4], bhi[1], blo[1]);
                    MMA_TF32(o[nt], ahi, bhi);
                    MMA_TF32(o[nt], ahi, blo);
                    MMA_TF32(o[nt], alo, bhi);
                }
            }
        }
    }

    if (wactive) {
        const float inv0 = 1.0f / l0, inv1 = 1.0f / l1;
        const int row0 = i0 + wm + r, row1 = row0 + 8;
#pragma unroll
        for (int nt = 0; nt < 8; nt++) {
            const int col = h * HD + nt * 8 + cq * 2;
            if (row0 < SS) {
                float2 ov = make_float2(tf32r(o[nt][0] * inv0), tf32r(o[nt][1] * inv0));
                *(float2*)&ctx[((size_t)b * SS + row0) * DD + col] = ov;
            }
            if (row1 < SS) {
                float2 ov = make_float2(tf32r(o[nt][2] * inv1), tf32r(o[nt][3] * inv1));
                *(float2*)&ctx[((size_t)b * SS + row1) * DD + col] = ov;
            }
        }
    }
}

// ---------------- classifier head ----------------
__global__ void head_kernel(const float* __restrict__ cls, const float* __restrict__ hw,
                            float* __restrict__ out)
{
    __shared__ float s[DD];
    int b = blockIdx.x;
    for (int k = threadIdx.x; k < DD; k += blockDim.x) s[k] = cls[(size_t)b * DD + k];
    __syncthreads();
    int c = threadIdx.x;
    if (c < NCLS) {
        const float* w = hw + (size_t)c * DD;
        float acc = 0.f;
#pragma unroll 8
        for (int k = 0; k < DD; k++) acc += s[k] * w[k];
        out[(size_t)b * NCLS + c] = acc;
    }
}

// ---------------- launch ----------------
extern "C" void kernel_launch(void* const* d_in, const int* in_sizes, int n_in,
                              void* d_out, int out_size) {
    const float* x         = (const float*)d_in[0];
    const float* patch_w   = (const float*)d_in[1];
    const float* patch_b   = (const float*)d_in[2];
    const float* cls_token = (const float*)d_in[3];
    const float* pos_embed = (const float*)d_in[4];
    const float* ln1_g     = (const float*)d_in[5];
    const float* ln1_b     = (const float*)d_in[6];
    const float* qkv_w     = (const float*)d_in[7];
    const float* qkv_b     = (const float*)d_in[8];
    const float* out_w     = (const float*)d_in[9];
    const float* out_b     = (const float*)d_in[10];
    const float* ln2_g     = (const float*)d_in[11];
    const float* ln2_b     = (const float*)d_in[12];
    const float* fc1_w     = (const float*)d_in[13];
    const float* fc1_b     = (const float*)d_in[14];
    const float* fc2_w     = (const float*)d_in[15];
    const float* fc2_b     = (const float*)d_in[16];
    const float* lnf_g     = (const float*)d_in[17];
    const float* lnf_b     = (const float*)d_in[18];
    const float* head_w    = (const float*)d_in[19];
    float* out = (float*)d_out;

    float *patches, *tok, *h, *xn, *qkv, *ctx, *hid, *cls, *w;
    cudaGetSymbolAddress((void**)&patches, g_patches);
    cudaGetSymbolAddress((void**)&tok, g_tok);
    cudaGetSymbolAddress((void**)&h, g_h);
    cudaGetSymbolAddress((void**)&xn, g_xn);
    cudaGetSymbolAddress((void**)&qkv, g_qkv);
    cudaGetSymbolAddress((void**)&ctx, g_ctx);
    cudaGetSymbolAddress((void**)&hid, g_hid);
    cudaGetSymbolAddress((void**)&cls, g_cls);
    cudaGetSymbolAddress((void**)&w, g_w);

    cudaFuncSetAttribute(gemm_tf32<0>, cudaFuncAttributeMaxDynamicSharedMemorySize, GEMM_SMEM);
    cudaFuncSetAttribute(gemm_tf32<1>, cudaFuncAttributeMaxDynamicSharedMemorySize, GEMM_SMEM);
    cudaFuncSetAttribute(gemm_tf32<2>, cudaFuncAttributeMaxDynamicSharedMemorySize, GEMM_SMEM);
    cudaFuncSetAttribute(flash_attn, cudaFuncAttributeMaxDynamicSharedMemorySize, FA_SMEM);

    // 0,1: weight rounding; 2: patchify; 3: patch GEMM (profiled index)
    round_w_a<<<(W_FC1 / 4 + 255) / 256, 256>>>(patch_w, qkv_w, out_w, w);
    round_w_b<<<((W_TOTAL - W_FC1) / 4 + 255) / 256, 256>>>(fc1_w, fc2_w, w);
    patchify_kernel<<<(PTOK * PATCH_DIM + 255) / 256, 256>>>(x, patches);
    gemm_tf32<0><<<dim3(DD / 128, PTOK / 128), 256, GEMM_SMEM>>>(
        patches, w + W_PATCH, patch_b, nullptr, tok, PTOK, DD, PATCH_DIM);
    assemble_kernel<<<(TOK * DD + 255) / 256, 256>>>(tok, cls_token, pos_embed, h);

    for (int i = 0; i < DEPTH; i++) {
        ln_warp_kernel<<<(TOK + 7) / 8, 256>>>(h, ln1_g + i * DD, ln1_b + i * DD, xn, DD, TOK);
        gemm_tf32<0><<<dim3(3 * DD / 128, TOK / 128), 256, GEMM_SMEM>>>(
            xn, w + W_QKV + (size_t)i * 3 * DD * DD, qkv_b + (size_t)i * 3 * DD,
            nullptr, qkv, TOK, 3 * DD, DD);
        flash_attn<<<dim3(2, BH), 256, FA_SMEM>>>(qkv, ctx);
        gemm_tf32<2><<<dim3(DD / 128, TOK / 128), 256, GEMM_SMEM>>>(
            ctx, w + W_OUT + (size_t)i * DD * DD, out_b + (size_t)i * DD, h, h, TOK, DD, DD);
        ln_warp_kernel<<<(TOK + 7) / 8, 256>>>(h, ln2_g + i * DD, ln2_b + i * DD, xn, DD, TOK);
        gemm_tf32<1><<<dim3(HID / 128, TOK / 128), 256, GEMM_SMEM>>>(
            xn, w + W_FC1 + (size_t)i * HID * DD, fc1_b + (size_t)i * HID,
            nullptr, hid, TOK, HID, DD);
        gemm_tf32<2><<<dim3(DD / 128, TOK / 128), 256, GEMM_SMEM>>>(
            hid, w + W_FC2 + (size_t)i * DD * HID, fc2_b + (size_t)i * DD, h, h, TOK, DD, HID);
    }

    ln_warp_kernel<<<(BB + 7) / 8, 256>>>(h, lnf_g, lnf_b, cls, (long)SS * DD, BB);
    head_kernel<<<BB, 128>>>(cls, head_w, out);
}

// round 15
// speedup vs baseline: 1.2176x; 1.0542x over previous
#include <cuda_runtime.h>
#include <math.h>
#include <stdint.h>

// ---------------- problem constants ----------------
#define BB 128
#define CC 3
#define IMG 224
#define PP 16
#define HP 14
#define NP 196
#define SS 197
#define DD 384
#define HEADS 6
#define HD 64
#define DEPTH 12
#define HID 1536
#define NCLS 100
#define PATCH_DIM 768
#define TOK (BB*SS)    // 25216
#define PTOK (BB*NP)   // 25088
#define BH (BB*HEADS)  // 768

// ---------------- scratch ----------------
__device__ float g_patches[PTOK * PATCH_DIM];
__device__ float g_tok[PTOK * DD];
__device__ float g_h[TOK * DD];
__device__ float g_xn[TOK * DD];
__device__ float g_qkv[TOK * 3 * DD];
__device__ float g_ctx[TOK * DD];
__device__ float g_hid[TOK * HID];
__device__ float g_cls[BB * DD];
// tf32-rounded weights (offsets in floats)
#define W_PATCH 0
#define W_QKV   294912
#define W_OUT   5603328
#define W_FC1   7372800
#define W_FC2   14450688
#define W_TOTAL 21528576
__device__ float g_w[W_TOTAL];

// ---------------- helpers ----------------
__device__ __forceinline__ float tf32r(float x) {
    uint32_t u;
    asm("cvt.rna.tf32.f32 %0, %1;" : "=r"(u) : "f"(x));
    return __uint_as_float(u);
}
__device__ __forceinline__ void split_u(float x, uint32_t& hi, uint32_t& lo) {
    float h = tf32r(x);
    hi = __float_as_uint(h);
    lo = __float_as_uint(tf32r(x - h));
}
__device__ __forceinline__ uint32_t smem_u32(const void* p) {
    return (uint32_t)__cvta_generic_to_shared(p);
}
#define CPA(dst, src) asm volatile("cp.async.cg.shared.global [%0], [%1], 16;" :: "r"(dst), "l"(src))
#define CPC() asm volatile("cp.async.commit_group;")
#define CPW0() asm volatile("cp.async.wait_group 0;")
#define CPW1() asm volatile("cp.async.wait_group 1;")
#define MMA_TF32_2(d, a, b0v, b1v) asm volatile( \
    "mma.sync.aligned.m16n8k8.row.col.f32.tf32.tf32.f32 " \
    "{%0,%1,%2,%3},{%4,%5,%6,%7},{%8,%9},{%0,%1,%2,%3};" \
    : "+f"(d[0]), "+f"(d[1]), "+f"(d[2]), "+f"(d[3]) \
    : "r"(a[0]), "r"(a[1]), "r"(a[2]), "r"(a[3]), "r"(b0v), "r"(b1v))
#define LDSM_X4(f, addr) asm volatile( \
    "ldmatrix.sync.aligned.m8n8.x4.shared.b16 {%0,%1,%2,%3}, [%4];" \
    : "=r"((f)[0]), "=r"((f)[1]), "=r"((f)[2]), "=r"((f)[3]) : "r"(addr))

// ---------------- weight rounding (2 launches for profiler indexing) ----------------
__global__ void round_w_a(const float* __restrict__ pw, const float* __restrict__ qw,
                          const float* __restrict__ ow, float* __restrict__ w) {
    int i = blockIdx.x * blockDim.x + threadIdx.x;
    if (i >= W_FC1 / 4) return;
    int f = i * 4;
    const float* src; int off;
    if (f < W_QKV)      { src = pw; off = f - W_PATCH; }
    else if (f < W_OUT) { src = qw; off = f - W_QKV; }
    else                { src = ow; off = f - W_OUT; }
    float4 v = *(const float4*)(src + off);
    v.x = tf32r(v.x); v.y = tf32r(v.y); v.z = tf32r(v.z); v.w = tf32r(v.w);
    ((float4*)w)[i] = v;
}
__global__ void round_w_b(const float* __restrict__ f1, const float* __restrict__ f2,
                          float* __restrict__ w) {
    int i = blockIdx.x * blockDim.x + threadIdx.x;
    if (i >= (W_TOTAL - W_FC1) / 4) return;
    int f = W_FC1 + i * 4;
    const float* src; int off;
    if (f < W_FC2) { src = f1; off = f - W_FC1; }
    else           { src = f2; off = f - W_FC2; }
    float4 v = *(const float4*)(src + off);
    v.x = tf32r(v.x); v.y = tf32r(v.y); v.z = tf32r(v.z); v.w = tf32r(v.w);
    ((float4*)(w + W_FC1))[i] = v;
}

// ---------------- patchify (+tf32 round) ----------------
__global__ void patchify_kernel(const float* __restrict__ x, float* __restrict__ patches) {
    int idx = blockIdx.x * blockDim.x + threadIdx.x;
    if (idx >= PTOK * PATCH_DIM) return;
    int t = idx / PATCH_DIM;
    int k = idx - t * PATCH_DIM;
    int b = t / NP;
    int n = t - b * NP;
    int ph = n / HP, pw = n - ph * HP;
    int c = k >> 8;
    int py = (k >> 4) & 15;
    int px = k & 15;
    patches[idx] = tf32r(x[(((size_t)b * CC + c) * IMG + (ph * PP + py)) * IMG + (pw * PP + px)]);
}

// ---------------- assemble h = [cls; tok] + pos ----------------
__global__ void assemble_kernel(const float* __restrict__ tok, const float* __restrict__ cls_token,
                                const float* __restrict__ pos, float* __restrict__ h) {
    int idx = blockIdx.x * blockDim.x + threadIdx.x;
    if (idx >= TOK * DD) return;
    int row = idx / DD;
    int d = idx - row * DD;
    int b = row / SS;
    int s = row - b * SS;
    float v = (s == 0) ? cls_token[d] : tok[((size_t)b * NP + (s - 1)) * DD + d];
    h[idx] = v + pos[s * DD + d];
}

// ---------------- tf32 NT GEMM: swizzled smem, 3-stage cp.async, ldmatrix fragments ----------------
#define GSTAGE 4096
#define GEMM_SMEM (3 * 2 * GSTAGE * 4)      // 98304 B

template <int OP>
__global__ void __launch_bounds__(256, 2) gemm_tf32(
    const float* __restrict__ A, const float* __restrict__ Bw,
    const float* __restrict__ bias, const float* __restrict__ res,
    float* __restrict__ C, int M, int N, int K)
{
    extern __shared__ float gsm[];
    float* As = gsm;
    float* Bs = gsm + 3 * GSTAGE;

    const int tid = threadIdx.x;
    const int lane = tid & 31, warp = tid >> 5;
    const int wm = (warp >> 1) * 32;
    const int wn = (warp & 1) * 64;
    const int r = lane >> 2, cq = lane & 3;
    const int m0 = blockIdx.y * 128, n0 = blockIdx.x * 128;

    const int lr = tid >> 3;
    const int lc = (tid & 7) * 4;
    const int sw = (lr & 7) * 4;
    const float* Ag = A + (size_t)(m0 + lr) * K + lc;
    const float* Bg = Bw + (size_t)(n0 + lr) * K + lc;
    uint32_t sA[3][4], sB[3][4];
#pragma unroll
    for (int s = 0; s < 3; s++)
#pragma unroll
        for (int c = 0; c < 4; c++) {
            sA[s][c] = smem_u32(As + (size_t)s * GSTAGE + (lr + c * 32) * 32 + (lc ^ sw));
            sB[s][c] = smem_u32(Bs + (size_t)s * GSTAGE + (lr + c * 32) * 32 + (lc ^ sw));
        }

    const int lm = lane >> 3;
    const int rit = lane & 7;
    const int arow0 = wm + ((lm & 1) * 8) + rit;
    const int abo = lm >> 1;
    const uint32_t aswz0 = (uint32_t)(arow0 & 7);
    const uint32_t aswz1 = (uint32_t)((arow0 + 16) & 7);
    const int bnt = lm >> 1;
    const int bbo = lm & 1;
    uint32_t browoff[4], bswz[4];
#pragma unroll
    for (int g = 0; g < 4; g++) {
        int brow = wn + (2 * g + bnt) * 8 + rit;
        browoff[g] = (uint32_t)(brow * 128);
        bswz[g] = (uint32_t)(brow & 7);
    }
    const uint32_t smemA0 = smem_u32(As);
    const uint32_t smemB0 = smem_u32(Bs);

    float acc[2][8][4];
#pragma unroll
    for (int mt = 0; mt < 2; mt++)
#pragma unroll
        for (int nt = 0; nt < 8; nt++)
#pragma unroll
            for (int i = 0; i < 4; i++) acc[mt][nt][i] = 0.f;

    const int KT = K / 32;
#pragma unroll
    for (int c = 0; c < 4; c++) {
        CPA(sA[0][c], Ag + (size_t)c * 32 * K);
        CPA(sB[0][c], Bg + (size_t)c * 32 * K);
    }
    CPC();
#pragma unroll
    for (int c = 0; c < 4; c++) {
        CPA(sA[1][c], Ag + (size_t)c * 32 * K + 32);
        CPA(sB[1][c], Bg + (size_t)c * 32 * K + 32);
    }
    CPC();

    for (int kt = 0; kt < KT; kt++) {
        if (kt + 1 < KT) { CPW1(); } else { CPW0(); }
        __syncthreads();
        if (kt + 2 < KT) {
            const int st = (kt + 2) % 3;
            const int ko = (kt + 2) * 32;
#pragma unroll
            for (int c = 0; c < 4; c++) {
                CPA(sA[st][c], Ag + (size_t)c * 32 * K + ko);
                CPA(sB[st][c], Bg + (size_t)c * 32 * K + ko);
            }
            CPC();
        }
        const int buf = kt % 3;
        const uint32_t abase = smemA0 + (uint32_t)buf * (GSTAGE * 4);
        const uint32_t bbase = smemB0 + (uint32_t)buf * (GSTAGE * 4);

#pragma unroll
        for (int ks = 0; ks < 4; ks++) {
            const uint32_t kb = (uint32_t)(ks * 2);
            uint32_t a[2][4], bf[4][4];
            LDSM_X4(a[0], abase + (uint32_t)(arow0 * 128) + (((kb + abo) ^ aswz0) << 4));
            LDSM_X4(a[1], abase + (uint32_t)((arow0 + 16) * 128) + (((kb + abo) ^ aswz1) << 4));
#pragma unroll
            for (int g = 0; g < 4; g++)
                LDSM_X4(bf[g], bbase + browoff[g] + (((kb + bbo) ^ bswz[g]) << 4));
#pragma unroll
            for (int mt = 0; mt < 2; mt++)
#pragma unroll
                for (int nt = 0; nt < 8; nt++)
                    MMA_TF32_2(acc[mt][nt], a[mt],
                               bf[nt >> 1][(nt & 1) * 2], bf[nt >> 1][(nt & 1) * 2 + 1]);
        }
    }

#pragma unroll
    for (int mt = 0; mt < 2; mt++) {
        const int row = m0 + wm + mt * 16 + r;
#pragma unroll
        for (int nt = 0; nt < 8; nt++) {
            const int col = n0 + wn + nt * 8 + cq * 2;
            const float2 bv = *(const float2*)(bias + col);
            float o0 = acc[mt][nt][0] + bv.x;
            float o1 = acc[mt][nt][1] + bv.y;
            float o2 = acc[mt][nt][2] + bv.x;
            float o3 = acc[mt][nt][3] + bv.y;
            if (OP == 1) {
                o0 = tf32r(0.5f * o0 * (1.0f + erff(o0 * 0.7071067811865475f)));
                o1 = tf32r(0.5f * o1 * (1.0f + erff(o1 * 0.7071067811865475f)));
                o2 = tf32r(0.5f * o2 * (1.0f + erff(o2 * 0.7071067811865475f)));
                o3 = tf32r(0.5f * o3 * (1.0f + erff(o3 * 0.7071067811865475f)));
            }
            if (OP == 2) {
                const float2 r0 = *(const float2*)(res + (size_t)row * N + col);
                const float2 r1 = *(const float2*)(res + (size_t)(row + 8) * N + col);
                o0 += r0.x; o1 += r0.y; o2 += r1.x; o3 += r1.y;
            }
            *(float2*)(C + (size_t)row * N + col) = make_float2(o0, o1);
            *(float2*)(C + (size_t)(row + 8) * N + col) = make_float2(o2, o3);
        }
    }
}

// ---------------- LayerNorm: one warp per row ----------------
__global__ void ln_warp_kernel(const float* __restrict__ x, const float* __restrict__ g,
                               const float* __restrict__ bt, float* __restrict__ y,
                               long in_row_stride, int nrows)
{
    const int row = blockIdx.x * 8 + (threadIdx.x >> 5);
    if (row >= nrows) return;
    const int lane = threadIdx.x & 31;
    const float4* xr = (const float4*)(x + (size_t)row * in_row_stride);
    float4 v[3];
    v[0] = xr[lane]; v[1] = xr[lane + 32]; v[2] = xr[lane + 64];
    float s = 0.f, q = 0.f;
#pragma unroll
    for (int t = 0; t < 3; t++) {
        s += v[t].x + v[t].y + v[t].z + v[t].w;
        q += v[t].x * v[t].x + v[t].y * v[t].y + v[t].z * v[t].z + v[t].w * v[t].w;
    }
#pragma unroll
    for (int o = 16; o; o >>= 1) {
        s += __shfl_xor_sync(0xffffffffu, s, o);
        q += __shfl_xor_sync(0xffffffffu, q, o);
    }
    const float mean = s * (1.0f / DD);
    const float rstd = rsqrtf(q * (1.0f / DD) - mean * mean + 1e-5f);
    const float4* gp = (const float4*)g;
    const float4* bp = (const float4*)bt;
    float4* yr = (float4*)(y + (size_t)row * DD);
#pragma unroll
    for (int t = 0; t < 3; t++) {
        float4 gv = gp[lane + 32 * t], bv = bp[lane + 32 * t];
        float4 o;
        o.x = tf32r((v[t].x - mean) * rstd * gv.x + bv.x);
        o.y = tf32r((v[t].y - mean) * rstd * gv.y + bv.y);
        o.z = tf32r((v[t].z - mean) * rstd * gv.z + bv.z);
        o.w = tf32r((v[t].w - mean) * rstd * gv.w + bv.w);
        yr[lane + 32 * t] = o;
    }
}

// ---------------- fused flash attention (R11 shape) + ldmatrix fragment loads ----------------
// fp32 smem tiles, split-at-use in REGISTERS after LDSM. Row stride 68 floats = 17x16B,
// 17 % 8 == 1 -> ldmatrix 8-row groups hit distinct 16B bank columns (conflict-free).
#define FA_SMEM ((128 + 64 + 64 + 128) * 68 * 4)

__global__ void __launch_bounds__(256, 2) flash_attn(const float* __restrict__ qkv,
                                                     float* __restrict__ ctx)
{
    extern __shared__ float sm[];
    float (*Qs)[68] = (float(*)[68])sm;
    float (*Ks)[68] = Qs + 128;
    float (*Vt)[68] = Ks + 64;
    float (*Ps)[68] = Vt + 64;

    const int bh = blockIdx.y;
    const int b = bh / HEADS, h = bh - b * HEADS;
    const int i0 = blockIdx.x * 128;
    const float* base = qkv + (size_t)b * SS * (3 * DD) + h * HD;

    const int tid = threadIdx.x;
    const int lane = tid & 31, warp = tid >> 5;
    const int wm = warp * 16;
    const int r = lane >> 2, cq = lane & 3;
    const bool wactive = (i0 + wm) < SS;

    // ldmatrix lane constants (R9-validated mapping)
    const int lm = lane >> 3;
    const int rit = lane & 7;
    const uint32_t a_rowoff = (uint32_t)((wm + (lm & 1) * 8 + rit) * 272);  // Q/P rows
    const uint32_t a_blk = (uint32_t)(lm >> 1);
    const uint32_t b_blk = (uint32_t)(lm & 1);
    uint32_t growb[4];                                                       // K/Vt rows
#pragma unroll
    for (int g = 0; g < 4; g++)
        growb[g] = (uint32_t)(((2 * g + (lm >> 1)) * 8 + rit) * 272);
    const uint32_t qs0 = smem_u32(Qs), ks0 = smem_u32(Ks);
    const uint32_t vt0 = smem_u32(Vt), ps0 = smem_u32(Ps);

    // load Q (128 x 64), scaled, fp32
    for (int idx = tid; idx < 128 * 16; idx += 256) {
        int ii = idx >> 4, d4 = (idx & 15) * 4;
        int i = i0 + ii;
        float4 v = make_float4(0.f, 0.f, 0.f, 0.f);
        if (i < SS) v = *(const float4*)(base + (size_t)i * (3 * DD) + d4);
        Qs[ii][d4 + 0] = v.x * 0.125f;
        Qs[ii][d4 + 1] = v.y * 0.125f;
        Qs[ii][d4 + 2] = v.z * 0.125f;
        Qs[ii][d4 + 3] = v.w * 0.125f;
    }

    float o[8][4];
#pragma unroll
    for (int nt = 0; nt < 8; nt++)
#pragma unroll
        for (int i = 0; i < 4; i++) o[nt][i] = 0.f;
    float m0 = -1e30f, m1 = -1e30f, l0 = 0.f, l1 = 0.f;

    for (int jc = 0; jc < 4; jc++) {
        const int jb = jc * 64;
        const int ntmax = (jc < 3) ? 8 : 1;
        __syncthreads();

        for (int idx = tid; idx < 64 * 16; idx += 256) {
            int jj = idx >> 4, d4 = (idx & 15) * 4;
            int j = jb + jj;
            float4 v = make_float4(0.f, 0.f, 0.f, 0.f);
            if (j < SS) v = *(const float4*)(base + (size_t)j * (3 * DD) + DD + d4);
            Ks[jj][d4 + 0] = v.x; Ks[jj][d4 + 1] = v.y;
            Ks[jj][d4 + 2] = v.z; Ks[jj][d4 + 3] = v.w;
        }
        for (int idx = tid; idx < 64 * 16; idx += 256) {
            int jj = idx >> 4, d4 = (idx & 15) * 4;
            int j = jb + jj;
            float4 v = make_float4(0.f, 0.f, 0.f, 0.f);
            if (j < SS) v = *(const float4*)(base + (size_t)j * (3 * DD) + 2 * DD + d4);
            Vt[d4 + 0][jj] = v.x; Vt[d4 + 1][jj] = v.y;
            Vt[d4 + 2][jj] = v.z; Vt[d4 + 3][jj] = v.w;
        }
        __syncthreads();

        if (wactive) {
            // ---- S = Q K^T: fragments via LDSM, split in registers ----
            float s[8][4];
#pragma unroll
            for (int nt = 0; nt < 8; nt++)
#pragma unroll
                for (int i = 0; i < 4; i++) s[nt][i] = 0.f;

            const int gmaxS = (ntmax + 1) >> 1;
#pragma unroll
            for (int k0 = 0; k0 < 64; k0 += 8) {
                const uint32_t akb = (uint32_t)(((k0 >> 2) + a_blk) << 4);
                const uint32_t bkb = (uint32_t)(((k0 >> 2) + b_blk) << 4);
                uint32_t araw[4], ahi[4], alo[4];
                LDSM_X4(araw, qs0 + a_rowoff + akb);
#pragma unroll
                for (int i = 0; i < 4; i++)
                    split_u(__uint_as_float(araw[i]), ahi[i], alo[i]);
                for (int g = 0; g < gmaxS; g++) {
                    uint32_t braw[4], bhi[4], blo[4];
                    LDSM_X4(braw, ks0 + growb[g] + bkb);
#pragma unroll
                    for (int i = 0; i < 4; i++)
                        split_u(__uint_as_float(braw[i]), bhi[i], blo[i]);
                    MMA_TF32_2(s[2 * g], ahi, bhi[0], bhi[1]);
                    MMA_TF32_2(s[2 * g], ahi, blo[0], blo[1]);
                    MMA_TF32_2(s[2 * g], alo, bhi[0], bhi[1]);
                    if (2 * g + 1 < ntmax) {
                        MMA_TF32_2(s[2 * g + 1], ahi, bhi[2], bhi[3]);
                        MMA_TF32_2(s[2 * g + 1], ahi, blo[2], blo[3]);
                        MMA_TF32_2(s[2 * g + 1], alo, bhi[2], bhi[3]);
                    }
                }
            }

            // ---- mask, rowwise max (quad), online softmax ----
            float mx0 = -1e30f, mx1 = -1e30f;
            for (int nt = 0; nt < ntmax; nt++) {
                int col = jb + nt * 8 + cq * 2;
                if (col >= SS)     { s[nt][0] = s[nt][2] = -1e30f; }
                if (col + 1 >= SS) { s[nt][1] = s[nt][3] = -1e30f; }
                mx0 = fmaxf(mx0, fmaxf(s[nt][0], s[nt][1]));
                mx1 = fmaxf(mx1, fmaxf(s[nt][2], s[nt][3]));
            }
            mx0 = fmaxf(mx0, __shfl_xor_sync(0xffffffffu, mx0, 1));
            mx0 = fmaxf(mx0, __shfl_xor_sync(0xffffffffu, mx0, 2));
            mx1 = fmaxf(mx1, __shfl_xor_sync(0xffffffffu, mx1, 1));
            mx1 = fmaxf(mx1, __shfl_xor_sync(0xffffffffu, mx1, 2));

            const float mn0 = fmaxf(m0, mx0), mn1 = fmaxf(m1, mx1);
            const float sc0 = __expf(m0 - mn0), sc1 = __expf(m1 - mn1);
            float sum0 = 0.f, sum1 = 0.f;
            for (int nt = 0; nt < ntmax; nt++) {
                int cc = nt * 8 + cq * 2;
                float p0 = __expf(s[nt][0] - mn0);
                float p1 = __expf(s[nt][1] - mn0);
                float p2 = __expf(s[nt][2] - mn1);
                float p3 = __expf(s[nt][3] - mn1);
                sum0 += p0 + p1;
                sum1 += p2 + p3;
                Ps[wm + r][cc] = p0;     Ps[wm + r][cc + 1] = p1;
                Ps[wm + r + 8][cc] = p2; Ps[wm + r + 8][cc + 1] = p3;
            }
            sum0 += __shfl_xor_sync(0xffffffffu, sum0, 1);
            sum0 += __shfl_xor_sync(0xffffffffu, sum0, 2);
            sum1 += __shfl_xor_sync(0xffffffffu, sum1, 1);
            sum1 += __shfl_xor_sync(0xffffffffu, sum1, 2);
            l0 = l0 * sc0 + sum0;
            l1 = l1 * sc1 + sum1;
            m0 = mn0; m1 = mn1;
#pragma unroll
            for (int nt = 0; nt < 8; nt++) {
                o[nt][0] *= sc0; o[nt][1] *= sc0;
                o[nt][2] *= sc1; o[nt][3] *= sc1;
            }
            __syncwarp();

            // ---- O += P V: fragments via LDSM, split in registers ----
            for (int k0 = 0; k0 < ntmax * 8; k0 += 8) {
                const uint32_t akb = (uint32_t)(((k0 >> 2) + a_blk) << 4);
                const uint32_t bkb = (uint32_t)(((k0 >> 2) + b_blk) << 4);
                uint32_t araw[4], ahi[4], alo[4];
                LDSM_X4(araw, ps0 + a_rowoff + akb);
#pragma unroll
                for (int i = 0; i < 4; i++)
                    split_u(__uint_as_float(araw[i]), ahi[i], alo[i]);
#pragma unroll
                for (int g = 0; g < 4; g++) {
                    uint32_t braw[4], bhi[4], blo[4];
                    LDSM_X4(braw, vt0 + growb[g] + bkb);
#pragma unroll
                    for (int i = 0; i < 4; i++)
                        split_u(__uint_as_float(braw[i]), bhi[i], blo[i]);
                    MMA_TF32_2(o[2 * g], ahi, bhi[0], bhi[1]);
                    MMA_TF32_2(o[2 * g], ahi, blo[0], blo[1]);
                    MMA_TF32_2(o[2 * g], alo, bhi[0], bhi[1]);
                    MMA_TF32_2(o[2 * g + 1], ahi, bhi[2], bhi[3]);
                    MMA_TF32_2(o[2 * g + 1], ahi, blo[2], blo[3]);
                    MMA_TF32_2(o[2 * g + 1], alo, bhi[2], bhi[3]);
                }
            }
        }
    }

    if (wactive) {
        const float inv0 = 1.0f / l0, inv1 = 1.0f / l1;
        const int row0 = i0 + wm + r, row1 = row0 + 8;
#pragma unroll
        for (int nt = 0; nt < 8; nt++) {
            const int col = h * HD + nt * 8 + cq * 2;
            if (row0 < SS) {
                float2 ov = make_float2(tf32r(o[nt][0] * inv0), tf32r(o[nt][1] * inv0));
                *(float2*)&ctx[((size_t)b * SS + row0) * DD + col] = ov;
            }
            if (row1 < SS) {
                float2 ov = make_float2(tf32r(o[nt][2] * inv1), tf32r(o[nt][3] * inv1));
                *(float2*)&ctx[((size_t)b * SS + row1) * DD + col] = ov;
            }
        }
    }
}

// ---------------- classifier head ----------------
__global__ void head_kernel(const float* __restrict__ cls, const float* __restrict__ hw,
                            float* __restrict__ out)
{
    __shared__ float s[DD];
    int b = blockIdx.x;
    for (int k = threadIdx.x; k < DD; k += blockDim.x) s[k] = cls[(size_t)b * DD + k];
    __syncthreads();
    int c = threadIdx.x;
    if (c < NCLS) {
        const float* w = hw + (size_t)c * DD;
        float acc = 0.f;
#pragma unroll 8
        for (int k = 0; k < DD; k++) acc += s[k] * w[k];
        out[(size_t)b * NCLS + c] = acc;
    }
}

// ---------------- launch ----------------
extern "C" void kernel_launch(void* const* d_in, const int* in_sizes, int n_in,
                              void* d_out, int out_size) {
    const float* x         = (const float*)d_in[0];
    const float* patch_w   = (const float*)d_in[1];
    const float* patch_b   = (const float*)d_in[2];
    const float* cls_token = (const float*)d_in[3];
    const float* pos_embed = (const float*)d_in[4];
    const float* ln1_g     = (const float*)d_in[5];
    const float* ln1_b     = (const float*)d_in[6];
    const float* qkv_w     = (const float*)d_in[7];
    const float* qkv_b     = (const float*)d_in[8];
    const float* out_w     = (const float*)d_in[9];
    const float* out_b     = (const float*)d_in[10];
    const float* ln2_g     = (const float*)d_in[11];
    const float* ln2_b     = (const float*)d_in[12];
    const float* fc1_w     = (const float*)d_in[13];
    const float* fc1_b     = (const float*)d_in[14];
    const float* fc2_w     = (const float*)d_in[15];
    const float* fc2_b     = (const float*)d_in[16];
    const float* lnf_g     = (const float*)d_in[17];
    const float* lnf_b     = (const float*)d_in[18];
    const float* head_w    = (const float*)d_in[19];
    float* out = (float*)d_out;

    float *patches, *tok, *h, *xn, *qkv, *ctx, *hid, *cls, *w;
    cudaGetSymbolAddress((void**)&patches, g_patches);
    cudaGetSymbolAddress((void**)&tok, g_tok);
    cudaGetSymbolAddress((void**)&h, g_h);
    cudaGetSymbolAddress((void**)&xn, g_xn);
    cudaGetSymbolAddress((void**)&qkv, g_qkv);
    cudaGetSymbolAddress((void**)&ctx, g_ctx);
    cudaGetSymbolAddress((void**)&hid, g_hid);
    cudaGetSymbolAddress((void**)&cls, g_cls);
    cudaGetSymbolAddress((void**)&w, g_w);

    cudaFuncSetAttribute(gemm_tf32<0>, cudaFuncAttributeMaxDynamicSharedMemorySize, GEMM_SMEM);
    cudaFuncSetAttribute(gemm_tf32<1>, cudaFuncAttributeMaxDynamicSharedMemorySize, GEMM_SMEM);
    cudaFuncSetAttribute(gemm_tf32<2>, cudaFuncAttributeMaxDynamicSharedMemorySize, GEMM_SMEM);
    cudaFuncSetAttribute(flash_attn, cudaFuncAttributeMaxDynamicSharedMemorySize, FA_SMEM);

    // 0,1: weight rounding; 2: patchify; 3: patch GEMM (profiled index)
    round_w_a<<<(W_FC1 / 4 + 255) / 256, 256>>>(patch_w, qkv_w, out_w, w);
    round_w_b<<<((W_TOTAL - W_FC1) / 4 + 255) / 256, 256>>>(fc1_w, fc2_w, w);
    patchify_kernel<<<(PTOK * PATCH_DIM + 255) / 256, 256>>>(x, patches);
    gemm_tf32<0><<<dim3(DD / 128, PTOK / 128), 256, GEMM_SMEM>>>(
        patches, w + W_PATCH, patch_b, nullptr, tok, PTOK, DD, PATCH_DIM);
    assemble_kernel<<<(TOK * DD + 255) / 256, 256>>>(tok, cls_token, pos_embed, h);

    for (int i = 0; i < DEPTH; i++) {
        ln_warp_kernel<<<(TOK + 7) / 8, 256>>>(h, ln1_g + i * DD, ln1_b + i * DD, xn, DD, TOK);
        gemm_tf32<0><<<dim3(3 * DD / 128, TOK / 128), 256, GEMM_SMEM>>>(
            xn, w + W_QKV + (size_t)i * 3 * DD * DD, qkv_b + (size_t)i * 3 * DD,
            nullptr, qkv, TOK, 3 * DD, DD);
        flash_attn<<<dim3(2, BH), 256, FA_SMEM>>>(qkv, ctx);
        gemm_tf32<2><<<dim3(DD / 128, TOK / 128), 256, GEMM_SMEM>>>(
            ctx, w + W_OUT + (size_t)i * DD * DD, out_b + (size_t)i * DD, h, h, TOK, DD, DD);
        ln_warp_kernel<<<(TOK + 7) / 8, 256>>>(h, ln2_g + i * DD, ln2_b + i * DD, xn, DD, TOK);
        gemm_tf32<1><<<dim3(HID / 128, TOK / 128), 256, GEMM_SMEM>>>(
            xn, w + W_FC1 + (size_t)i * HID * DD, fc1_b + (size_t)i * HID,
            nullptr, hid, TOK, HID, DD);
        gemm_tf32<2><<<dim3(DD / 128, TOK / 128), 256, GEMM_SMEM>>>(
            hid, w + W_FC2 + (size_t)i * DD * HID, fc2_b + (size_t)i * DD, h, h, TOK, DD, HID);
    }

    ln_warp_kernel<<<(BB + 7) / 8, 256>>>(h, lnf_g, lnf_b, cls, (long)SS * DD, BB);
    head_kernel<<<BB, 128>>>(cls, head_w, out);
}

// round 16
// speedup vs baseline: 1.2616x; 1.0361x over previous
#include <cuda_runtime.h>
#include <math.h>
#include <stdint.h>

// ---------------- problem constants ----------------
#define BB 128
#define CC 3
#define IMG 224
#define PP 16
#define HP 14
#define NP 196
#define SS 197
#define DD 384
#define HEADS 6
#define HD 64
#define DEPTH 12
#define HID 1536
#define NCLS 100
#define PATCH_DIM 768
#define TOK (BB*SS)    // 25216
#define PTOK (BB*NP)   // 25088
#define BH (BB*HEADS)  // 768

// ---------------- scratch ----------------
__device__ float g_patches[PTOK * PATCH_DIM];
__device__ float g_tok[PTOK * DD];
__device__ float g_h[TOK * DD];
__device__ float g_xn[TOK * DD];
__device__ float g_qkv[TOK * 3 * DD];
__device__ float g_ctx[TOK * DD];
__device__ float g_hid[TOK * HID];
__device__ float g_cls[BB * DD];
// tf32-rounded weights (offsets in floats)
#define W_PATCH 0
#define W_QKV   294912
#define W_OUT   5603328
#define W_FC1   7372800
#define W_FC2   14450688
#define W_TOTAL 21528576
__device__ float g_w[W_TOTAL];

// ---------------- helpers ----------------
__device__ __forceinline__ float tf32r(float x) {
    uint32_t u;
    asm("cvt.rna.tf32.f32 %0, %1;" : "=r"(u) : "f"(x));
    return __uint_as_float(u);
}
__device__ __forceinline__ void split_u(float x, uint32_t& hi, uint32_t& lo) {
    float h = tf32r(x);
    hi = __float_as_uint(h);
    lo = __float_as_uint(tf32r(x - h));
}
__device__ __forceinline__ uint32_t smem_u32(const void* p) {
    return (uint32_t)__cvta_generic_to_shared(p);
}
#define CPA(dst, src) asm volatile("cp.async.cg.shared.global [%0], [%1], 16;" :: "r"(dst), "l"(src))
#define CPC() asm volatile("cp.async.commit_group;")
#define CPW0() asm volatile("cp.async.wait_group 0;")
#define CPW1() asm volatile("cp.async.wait_group 1;")
#define MMA_TF32_2(d, a, b0v, b1v) asm volatile( \
    "mma.sync.aligned.m16n8k8.row.col.f32.tf32.tf32.f32 " \
    "{%0,%1,%2,%3},{%4,%5,%6,%7},{%8,%9},{%0,%1,%2,%3};" \
    : "+f"(d[0]), "+f"(d[1]), "+f"(d[2]), "+f"(d[3]) \
    : "r"(a[0]), "r"(a[1]), "r"(a[2]), "r"(a[3]), "r"(b0v), "r"(b1v))
#define LDSM_X4(f, addr) asm volatile( \
    "ldmatrix.sync.aligned.m8n8.x4.shared.b16 {%0,%1,%2,%3}, [%4];" \
    : "=r"((f)[0]), "=r"((f)[1]), "=r"((f)[2]), "=r"((f)[3]) : "r"(addr))

// ---------------- weight rounding (2 launches for profiler indexing) ----------------
__global__ void round_w_a(const float* __restrict__ pw, const float* __restrict__ qw,
                          const float* __restrict__ ow, float* __restrict__ w) {
    int i = blockIdx.x * blockDim.x + threadIdx.x;
    if (i >= W_FC1 / 4) return;
    int f = i * 4;
    const float* src; int off;
    if (f < W_QKV)      { src = pw; off = f - W_PATCH; }
    else if (f < W_OUT) { src = qw; off = f - W_QKV; }
    else                { src = ow; off = f - W_OUT; }
    float4 v = *(const float4*)(src + off);
    v.x = tf32r(v.x); v.y = tf32r(v.y); v.z = tf32r(v.z); v.w = tf32r(v.w);
    ((float4*)w)[i] = v;
}
__global__ void round_w_b(const float* __restrict__ f1, const float* __restrict__ f2,
                          float* __restrict__ w) {
    int i = blockIdx.x * blockDim.x + threadIdx.x;
    if (i >= (W_TOTAL - W_FC1) / 4) return;
    int f = W_FC1 + i * 4;
    const float* src; int off;
    if (f < W_FC2) { src = f1; off = f - W_FC1; }
    else           { src = f2; off = f - W_FC2; }
    float4 v = *(const float4*)(src + off);
    v.x = tf32r(v.x); v.y = tf32r(v.y); v.z = tf32r(v.z); v.w = tf32r(v.w);
    ((float4*)(w + W_FC1))[i] = v;
}

// ---------------- patchify (+tf32 round) ----------------
__global__ void patchify_kernel(const float* __restrict__ x, float* __restrict__ patches) {
    int idx = blockIdx.x * blockDim.x + threadIdx.x;
    if (idx >= PTOK * PATCH_DIM) return;
    int t = idx / PATCH_DIM;
    int k = idx - t * PATCH_DIM;
    int b = t / NP;
    int n = t - b * NP;
    int ph = n / HP, pw = n - ph * HP;
    int c = k >> 8;
    int py = (k >> 4) & 15;
    int px = k & 15;
    patches[idx] = tf32r(x[(((size_t)b * CC + c) * IMG + (ph * PP + py)) * IMG + (pw * PP + px)]);
}

// ---------------- assemble h = [cls; tok] + pos ----------------
__global__ void assemble_kernel(const float* __restrict__ tok, const float* __restrict__ cls_token,
                                const float* __restrict__ pos, float* __restrict__ h) {
    int idx = blockIdx.x * blockDim.x + threadIdx.x;
    if (idx >= TOK * DD) return;
    int row = idx / DD;
    int d = idx - row * DD;
    int b = row / SS;
    int s = row - b * SS;
    float v = (s == 0) ? cls_token[d] : tok[((size_t)b * NP + (s - 1)) * DD + d];
    h[idx] = v + pos[s * DD + d];
}

// ---------------- tf32 NT GEMM: swizzled smem, 3-stage cp.async, ldmatrix fragments ----------------
#define GSTAGE 4096
#define GEMM_SMEM (3 * 2 * GSTAGE * 4)      // 98304 B

template <int OP>
__global__ void __launch_bounds__(256, 2) gemm_tf32(
    const float* __restrict__ A, const float* __restrict__ Bw,
    const float* __restrict__ bias, const float* __restrict__ res,
    float* __restrict__ C, int M, int N, int K)
{
    extern __shared__ float gsm[];
    float* As = gsm;
    float* Bs = gsm + 3 * GSTAGE;

    const int tid = threadIdx.x;
    const int lane = tid & 31, warp = tid >> 5;
    const int wm = (warp >> 1) * 32;
    const int wn = (warp & 1) * 64;
    const int r = lane >> 2, cq = lane & 3;
    const int m0 = blockIdx.y * 128, n0 = blockIdx.x * 128;

    const int lr = tid >> 3;
    const int lc = (tid & 7) * 4;
    const int sw = (lr & 7) * 4;
    const float* Ag = A + (size_t)(m0 + lr) * K + lc;
    const float* Bg = Bw + (size_t)(n0 + lr) * K + lc;
    uint32_t sA[3][4], sB[3][4];
#pragma unroll
    for (int s = 0; s < 3; s++)
#pragma unroll
        for (int c = 0; c < 4; c++) {
            sA[s][c] = smem_u32(As + (size_t)s * GSTAGE + (lr + c * 32) * 32 + (lc ^ sw));
            sB[s][c] = smem_u32(Bs + (size_t)s * GSTAGE + (lr + c * 32) * 32 + (lc ^ sw));
        }

    const int lm = lane >> 3;
    const int rit = lane & 7;
    const int arow0 = wm + ((lm & 1) * 8) + rit;
    const int abo = lm >> 1;
    const uint32_t aswz0 = (uint32_t)(arow0 & 7);
    const uint32_t aswz1 = (uint32_t)((arow0 + 16) & 7);
    const int bnt = lm >> 1;
    const int bbo = lm & 1;
    uint32_t browoff[4], bswz[4];
#pragma unroll
    for (int g = 0; g < 4; g++) {
        int brow = wn + (2 * g + bnt) * 8 + rit;
        browoff[g] = (uint32_t)(brow * 128);
        bswz[g] = (uint32_t)(brow & 7);
    }
    const uint32_t smemA0 = smem_u32(As);
    const uint32_t smemB0 = smem_u32(Bs);

    float acc[2][8][4];
#pragma unroll
    for (int mt = 0; mt < 2; mt++)
#pragma unroll
        for (int nt = 0; nt < 8; nt++)
#pragma unroll
            for (int i = 0; i < 4; i++) acc[mt][nt][i] = 0.f;

    const int KT = K / 32;
#pragma unroll
    for (int c = 0; c < 4; c++) {
        CPA(sA[0][c], Ag + (size_t)c * 32 * K);
        CPA(sB[0][c], Bg + (size_t)c * 32 * K);
    }
    CPC();
#pragma unroll
    for (int c = 0; c < 4; c++) {
        CPA(sA[1][c], Ag + (size_t)c * 32 * K + 32);
        CPA(sB[1][c], Bg + (size_t)c * 32 * K + 32);
    }
    CPC();

    for (int kt = 0; kt < KT; kt++) {
        if (kt + 1 < KT) { CPW1(); } else { CPW0(); }
        __syncthreads();
        if (kt + 2 < KT) {
            const int st = (kt + 2) % 3;
            const int ko = (kt + 2) * 32;
#pragma unroll
            for (int c = 0; c < 4; c++) {
                CPA(sA[st][c], Ag + (size_t)c * 32 * K + ko);
                CPA(sB[st][c], Bg + (size_t)c * 32 * K + ko);
            }
            CPC();
        }
        const int buf = kt % 3;
        const uint32_t abase = smemA0 + (uint32_t)buf * (GSTAGE * 4);
        const uint32_t bbase = smemB0 + (uint32_t)buf * (GSTAGE * 4);

#pragma unroll
        for (int ks = 0; ks < 4; ks++) {
            const uint32_t kb = (uint32_t)(ks * 2);
            uint32_t a[2][4], bf[4][4];
            LDSM_X4(a[0], abase + (uint32_t)(arow0 * 128) + (((kb + abo) ^ aswz0) << 4));
            LDSM_X4(a[1], abase + (uint32_t)((arow0 + 16) * 128) + (((kb + abo) ^ aswz1) << 4));
#pragma unroll
            for (int g = 0; g < 4; g++)
                LDSM_X4(bf[g], bbase + browoff[g] + (((kb + bbo) ^ bswz[g]) << 4));
#pragma unroll
            for (int mt = 0; mt < 2; mt++)
#pragma unroll
                for (int nt = 0; nt < 8; nt++)
                    MMA_TF32_2(acc[mt][nt], a[mt],
                               bf[nt >> 1][(nt & 1) * 2], bf[nt >> 1][(nt & 1) * 2 + 1]);
        }
    }

#pragma unroll
    for (int mt = 0; mt < 2; mt++) {
        const int row = m0 + wm + mt * 16 + r;
#pragma unroll
        for (int nt = 0; nt < 8; nt++) {
            const int col = n0 + wn + nt * 8 + cq * 2;
            const float2 bv = *(const float2*)(bias + col);
            float o0 = acc[mt][nt][0] + bv.x;
            float o1 = acc[mt][nt][1] + bv.y;
            float o2 = acc[mt][nt][2] + bv.x;
            float o3 = acc[mt][nt][3] + bv.y;
            if (OP == 1) {
                o0 = tf32r(0.5f * o0 * (1.0f + erff(o0 * 0.7071067811865475f)));
                o1 = tf32r(0.5f * o1 * (1.0f + erff(o1 * 0.7071067811865475f)));
                o2 = tf32r(0.5f * o2 * (1.0f + erff(o2 * 0.7071067811865475f)));
                o3 = tf32r(0.5f * o3 * (1.0f + erff(o3 * 0.7071067811865475f)));
            }
            if (OP == 2) {
                const float2 r0 = *(const float2*)(res + (size_t)row * N + col);
                const float2 r1 = *(const float2*)(res + (size_t)(row + 8) * N + col);
                o0 += r0.x; o1 += r0.y; o2 += r1.x; o3 += r1.y;
            }
            *(float2*)(C + (size_t)row * N + col) = make_float2(o0, o1);
            *(float2*)(C + (size_t)(row + 8) * N + col) = make_float2(o2, o3);
        }
    }
}

// ---------------- LayerNorm: one warp per row ----------------
__global__ void ln_warp_kernel(const float* __restrict__ x, const float* __restrict__ g,
                               const float* __restrict__ bt, float* __restrict__ y,
                               long in_row_stride, int nrows)
{
    const int row = blockIdx.x * 8 + (threadIdx.x >> 5);
    if (row >= nrows) return;
    const int lane = threadIdx.x & 31;
    const float4* xr = (const float4*)(x + (size_t)row * in_row_stride);
    float4 v[3];
    v[0] = xr[lane]; v[1] = xr[lane + 32]; v[2] = xr[lane + 64];
    float s = 0.f, q = 0.f;
#pragma unroll
    for (int t = 0; t < 3; t++) {
        s += v[t].x + v[t].y + v[t].z + v[t].w;
        q += v[t].x * v[t].x + v[t].y * v[t].y + v[t].z * v[t].z + v[t].w * v[t].w;
    }
#pragma unroll
    for (int o = 16; o; o >>= 1) {
        s += __shfl_xor_sync(0xffffffffu, s, o);
        q += __shfl_xor_sync(0xffffffffu, q, o);
    }
    const float mean = s * (1.0f / DD);
    const float rstd = rsqrtf(q * (1.0f / DD) - mean * mean + 1e-5f);
    const float4* gp = (const float4*)g;
    const float4* bp = (const float4*)bt;
    float4* yr = (float4*)(y + (size_t)row * DD);
#pragma unroll
    for (int t = 0; t < 3; t++) {
        float4 gv = gp[lane + 32 * t], bv = bp[lane + 32 * t];
        float4 o;
        o.x = tf32r((v[t].x - mean) * rstd * gv.x + bv.x);
        o.y = tf32r((v[t].y - mean) * rstd * gv.y + bv.y);
        o.z = tf32r((v[t].z - mean) * rstd * gv.z + bv.z);
        o.w = tf32r((v[t].w - mean) * rstd * gv.w + bv.w);
        yr[lane + 32 * t] = o;
    }
}

// ---------------- fused flash attention: 3xTF32 for S, plain tf32 for PV ----------------
#define FA_SMEM ((128 + 64 + 64 + 128) * 68 * 4)

__global__ void __launch_bounds__(256, 2) flash_attn(const float* __restrict__ qkv,
                                                     float* __restrict__ ctx)
{
    extern __shared__ float sm[];
    float (*Qs)[68] = (float(*)[68])sm;
    float (*Ks)[68] = Qs + 128;
    float (*Vt)[68] = Ks + 64;
    float (*Ps)[68] = Vt + 64;

    const int bh = blockIdx.y;
    const int b = bh / HEADS, h = bh - b * HEADS;
    const int i0 = blockIdx.x * 128;
    const float* base = qkv + (size_t)b * SS * (3 * DD) + h * HD;

    const int tid = threadIdx.x;
    const int lane = tid & 31, warp = tid >> 5;
    const int wm = warp * 16;
    const int r = lane >> 2, cq = lane & 3;
    const bool wactive = (i0 + wm) < SS;

    // ldmatrix lane constants (validated mapping)
    const int lm = lane >> 3;
    const int rit = lane & 7;
    const uint32_t a_rowoff = (uint32_t)((wm + (lm & 1) * 8 + rit) * 272);
    const uint32_t a_blk = (uint32_t)(lm >> 1);
    const uint32_t b_blk = (uint32_t)(lm & 1);
    uint32_t growb[4];
#pragma unroll
    for (int g = 0; g < 4; g++)
        growb[g] = (uint32_t)(((2 * g + (lm >> 1)) * 8 + rit) * 272);
    const uint32_t qs0 = smem_u32(Qs), ks0 = smem_u32(Ks);
    const uint32_t vt0 = smem_u32(Vt), ps0 = smem_u32(Ps);

    // load Q (128 x 64), scaled, fp32
    for (int idx = tid; idx < 128 * 16; idx += 256) {
        int ii = idx >> 4, d4 = (idx & 15) * 4;
        int i = i0 + ii;
        float4 v = make_float4(0.f, 0.f, 0.f, 0.f);
        if (i < SS) v = *(const float4*)(base + (size_t)i * (3 * DD) + d4);
        Qs[ii][d4 + 0] = v.x * 0.125f;
        Qs[ii][d4 + 1] = v.y * 0.125f;
        Qs[ii][d4 + 2] = v.z * 0.125f;
        Qs[ii][d4 + 3] = v.w * 0.125f;
    }

    float o[8][4];
#pragma unroll
    for (int nt = 0; nt < 8; nt++)
#pragma unroll
        for (int i = 0; i < 4; i++) o[nt][i] = 0.f;
    float m0 = -1e30f, m1 = -1e30f, l0 = 0.f, l1 = 0.f;

    for (int jc = 0; jc < 4; jc++) {
        const int jb = jc * 64;
        const int ntmax = (jc < 3) ? 8 : 1;
        __syncthreads();

        for (int idx = tid; idx < 64 * 16; idx += 256) {
            int jj = idx >> 4, d4 = (idx & 15) * 4;
            int j = jb + jj;
            float4 v = make_float4(0.f, 0.f, 0.f, 0.f);
            if (j < SS) v = *(const float4*)(base + (size_t)j * (3 * DD) + DD + d4);
            Ks[jj][d4 + 0] = v.x; Ks[jj][d4 + 1] = v.y;
            Ks[jj][d4 + 2] = v.z; Ks[jj][d4 + 3] = v.w;
        }
        for (int idx = tid; idx < 64 * 16; idx += 256) {
            int jj = idx >> 4, d4 = (idx & 15) * 4;
            int j = jb + jj;
            float4 v = make_float4(0.f, 0.f, 0.f, 0.f);
            if (j < SS) v = *(const float4*)(base + (size_t)j * (3 * DD) + 2 * DD + d4);
            Vt[d4 + 0][jj] = v.x; Vt[d4 + 1][jj] = v.y;
            Vt[d4 + 2][jj] = v.z; Vt[d4 + 3][jj] = v.w;
        }
        __syncthreads();

        if (wactive) {
            // ---- S = Q K^T: 3xTF32 (exp-sensitive), fragments via LDSM ----
            float s[8][4];
#pragma unroll
            for (int nt = 0; nt < 8; nt++)
#pragma unroll
                for (int i = 0; i < 4; i++) s[nt][i] = 0.f;

            const int gmaxS = (ntmax + 1) >> 1;
#pragma unroll
            for (int k0 = 0; k0 < 64; k0 += 8) {
                const uint32_t akb = (uint32_t)(((k0 >> 2) + a_blk) << 4);
                const uint32_t bkb = (uint32_t)(((k0 >> 2) + b_blk) << 4);
                uint32_t araw[4], ahi[4], alo[4];
                LDSM_X4(araw, qs0 + a_rowoff + akb);
#pragma unroll
                for (int i = 0; i < 4; i++)
                    split_u(__uint_as_float(araw[i]), ahi[i], alo[i]);
                for (int g = 0; g < gmaxS; g++) {
                    uint32_t braw[4], bhi[4], blo[4];
                    LDSM_X4(braw, ks0 + growb[g] + bkb);
#pragma unroll
                    for (int i = 0; i < 4; i++)
                        split_u(__uint_as_float(braw[i]), bhi[i], blo[i]);
                    MMA_TF32_2(s[2 * g], ahi, bhi[0], bhi[1]);
                    MMA_TF32_2(s[2 * g], ahi, blo[0], blo[1]);
                    MMA_TF32_2(s[2 * g], alo, bhi[0], bhi[1]);
                    if (2 * g + 1 < ntmax) {
                        MMA_TF32_2(s[2 * g + 1], ahi, bhi[2], bhi[3]);
                        MMA_TF32_2(s[2 * g + 1], ahi, blo[2], blo[3]);
                        MMA_TF32_2(s[2 * g + 1], alo, bhi[2], bhi[3]);
                    }
                }
            }

            // ---- mask, rowwise max (quad), online softmax ----
            float mx0 = -1e30f, mx1 = -1e30f;
            for (int nt = 0; nt < ntmax; nt++) {
                int col = jb + nt * 8 + cq * 2;
                if (col >= SS)     { s[nt][0] = s[nt][2] = -1e30f; }
                if (col + 1 >= SS) { s[nt][1] = s[nt][3] = -1e30f; }
                mx0 = fmaxf(mx0, fmaxf(s[nt][0], s[nt][1]));
                mx1 = fmaxf(mx1, fmaxf(s[nt][2], s[nt][3]));
            }
            mx0 = fmaxf(mx0, __shfl_xor_sync(0xffffffffu, mx0, 1));
            mx0 = fmaxf(mx0, __shfl_xor_sync(0xffffffffu, mx0, 2));
            mx1 = fmaxf(mx1, __shfl_xor_sync(0xffffffffu, mx1, 1));
            mx1 = fmaxf(mx1, __shfl_xor_sync(0xffffffffu, mx1, 2));

            const float mn0 = fmaxf(m0, mx0), mn1 = fmaxf(m1, mx1);
            const float sc0 = __expf(m0 - mn0), sc1 = __expf(m1 - mn1);
            float sum0 = 0.f, sum1 = 0.f;
            for (int nt = 0; nt < ntmax; nt++) {
                int cc = nt * 8 + cq * 2;
                float p0 = __expf(s[nt][0] - mn0);
                float p1 = __expf(s[nt][1] - mn0);
                float p2 = __expf(s[nt][2] - mn1);
                float p3 = __expf(s[nt][3] - mn1);
                sum0 += p0 + p1;
                sum1 += p2 + p3;
                Ps[wm + r][cc] = p0;     Ps[wm + r][cc + 1] = p1;
                Ps[wm + r + 8][cc] = p2; Ps[wm + r + 8][cc + 1] = p3;
            }
            sum0 += __shfl_xor_sync(0xffffffffu, sum0, 1);
            sum0 += __shfl_xor_sync(0xffffffffu, sum0, 2);
            sum1 += __shfl_xor_sync(0xffffffffu, sum1, 1);
            sum1 += __shfl_xor_sync(0xffffffffu, sum1, 2);
            l0 = l0 * sc0 + sum0;
            l1 = l1 * sc1 + sum1;
            m0 = mn0; m1 = mn1;
#pragma unroll
            for (int nt = 0; nt < 8; nt++) {
                o[nt][0] *= sc0; o[nt][1] *= sc0;
                o[nt][2] *= sc1; o[nt][3] *= sc1;
            }
            __syncwarp();

            // ---- O += P V: PLAIN tf32 (P in [0,1], no exp amplification) ----
            // raw fp32 bits used directly as tf32 operands (HW truncation)
            for (int k0 = 0; k0 < ntmax * 8; k0 += 8) {
                const uint32_t akb = (uint32_t)(((k0 >> 2) + a_blk) << 4);
                const uint32_t bkb = (uint32_t)(((k0 >> 2) + b_blk) << 4);
                uint32_t araw[4];
                LDSM_X4(araw, ps0 + a_rowoff + akb);
#pragma unroll
                for (int g = 0; g < 4; g++) {
                    uint32_t braw[4];
                    LDSM_X4(braw, vt0 + growb[g] + bkb);
                    MMA_TF32_2(o[2 * g],     araw, braw[0], braw[1]);
                    MMA_TF32_2(o[2 * g + 1], araw, braw[2], braw[3]);
                }
            }
        }
    }

    if (wactive) {
        const float inv0 = 1.0f / l0, inv1 = 1.0f / l1;
        const int row0 = i0 + wm + r, row1 = row0 + 8;
#pragma unroll
        for (int nt = 0; nt < 8; nt++) {
            const int col = h * HD + nt * 8 + cq * 2;
            if (row0 < SS) {
                float2 ov = make_float2(tf32r(o[nt][0] * inv0), tf32r(o[nt][1] * inv0));
                *(float2*)&ctx[((size_t)b * SS + row0) * DD + col] = ov;
            }
            if (row1 < SS) {
                float2 ov = make_float2(tf32r(o[nt][2] * inv1), tf32r(o[nt][3] * inv1));
                *(float2*)&ctx[((size_t)b * SS + row1) * DD + col] = ov;
            }
        }
    }
}

// ---------------- classifier head ----------------
__global__ void head_kernel(const float* __restrict__ cls, const float* __restrict__ hw,
                            float* __restrict__ out)
{
    __shared__ float s[DD];
    int b = blockIdx.x;
    for (int k = threadIdx.x; k < DD; k += blockDim.x) s[k] = cls[(size_t)b * DD + k];
    __syncthreads();
    int c = threadIdx.x;
    if (c < NCLS) {
        const float* w = hw + (size_t)c * DD;
        float acc = 0.f;
#pragma unroll 8
        for (int k = 0; k < DD; k++) acc += s[k] * w[k];
        out[(size_t)b * NCLS + c] = acc;
    }
}

// ---------------- launch ----------------
extern "C" void kernel_launch(void* const* d_in, const int* in_sizes, int n_in,
                              void* d_out, int out_size) {
    const float* x         = (const float*)d_in[0];
    const float* patch_w   = (const float*)d_in[1];
    const float* patch_b   = (const float*)d_in[2];
    const float* cls_token = (const float*)d_in[3];
    const float* pos_embed = (const float*)d_in[4];
    const float* ln1_g     = (const float*)d_in[5];
    const float* ln1_b     = (const float*)d_in[6];
    const float* qkv_w     = (const float*)d_in[7];
    const float* qkv_b     = (const float*)d_in[8];
    const float* out_w     = (const float*)d_in[9];
    const float* out_b     = (const float*)d_in[10];
    const float* ln2_g     = (const float*)d_in[11];
    const float* ln2_b     = (const float*)d_in[12];
    const float* fc1_w     = (const float*)d_in[13];
    const float* fc1_b     = (const float*)d_in[14];
    const float* fc2_w     = (const float*)d_in[15];
    const float* fc2_b     = (const float*)d_in[16];
    const float* lnf_g     = (const float*)d_in[17];
    const float* lnf_b     = (const float*)d_in[18];
    const float* head_w    = (const float*)d_in[19];
    float* out = (float*)d_out;

    float *patches, *tok, *h, *xn, *qkv, *ctx, *hid, *cls, *w;
    cudaGetSymbolAddress((void**)&patches, g_patches);
    cudaGetSymbolAddress((void**)&tok, g_tok);
    cudaGetSymbolAddress((void**)&h, g_h);
    cudaGetSymbolAddress((void**)&xn, g_xn);
    cudaGetSymbolAddress((void**)&qkv, g_qkv);
    cudaGetSymbolAddress((void**)&ctx, g_ctx);
    cudaGetSymbolAddress((void**)&hid, g_hid);
    cudaGetSymbolAddress((void**)&cls, g_cls);
    cudaGetSymbolAddress((void**)&w, g_w);

    cudaFuncSetAttribute(gemm_tf32<0>, cudaFuncAttributeMaxDynamicSharedMemorySize, GEMM_SMEM);
    cudaFuncSetAttribute(gemm_tf32<1>, cudaFuncAttributeMaxDynamicSharedMemorySize, GEMM_SMEM);
    cudaFuncSetAttribute(gemm_tf32<2>, cudaFuncAttributeMaxDynamicSharedMemorySize, GEMM_SMEM);
    cudaFuncSetAttribute(flash_attn, cudaFuncAttributeMaxDynamicSharedMemorySize, FA_SMEM);

    // 0,1: weight rounding; 2: patchify; 3: patch GEMM (profiled index)
    round_w_a<<<(W_FC1 / 4 + 255) / 256, 256>>>(patch_w, qkv_w, out_w, w);
    round_w_b<<<((W_TOTAL - W_FC1) / 4 + 255) / 256, 256>>>(fc1_w, fc2_w, w);
    patchify_kernel<<<(PTOK * PATCH_DIM + 255) / 256, 256>>>(x, patches);
    gemm_tf32<0><<<dim3(DD / 128, PTOK / 128), 256, GEMM_SMEM>>>(
        patches, w + W_PATCH, patch_b, nullptr, tok, PTOK, DD, PATCH_DIM);
    assemble_kernel<<<(TOK * DD + 255) / 256, 256>>>(tok, cls_token, pos_embed, h);

    for (int i = 0; i < DEPTH; i++) {
        ln_warp_kernel<<<(TOK + 7) / 8, 256>>>(h, ln1_g + i * DD, ln1_b + i * DD, xn, DD, TOK);
        gemm_tf32<0><<<dim3(3 * DD / 128, TOK / 128), 256, GEMM_SMEM>>>(
            xn, w + W_QKV + (size_t)i * 3 * DD * DD, qkv_b + (size_t)i * 3 * DD,
            nullptr, qkv, TOK, 3 * DD, DD);
        flash_attn<<<dim3(2, BH), 256, FA_SMEM>>>(qkv, ctx);
        gemm_tf32<2><<<dim3(DD / 128, TOK / 128), 256, GEMM_SMEM>>>(
            ctx, w + W_OUT + (size_t)i * DD * DD, out_b + (size_t)i * DD, h, h, TOK, DD, DD);
        ln_warp_kernel<<<(TOK + 7) / 8, 256>>>(h, ln2_g + i * DD, ln2_b + i * DD, xn, DD, TOK);
        gemm_tf32<1><<<dim3(HID / 128, TOK / 128), 256, GEMM_SMEM>>>(
            xn, w + W_FC1 + (size_t)i * HID * DD, fc1_b + (size_t)i * HID,
            nullptr, hid, TOK, HID, DD);
        gemm_tf32<2><<<dim3(DD / 128, TOK / 128), 256, GEMM_SMEM>>>(
            hid, w + W_FC2 + (size_t)i * DD * HID, fc2_b + (size_t)i * DD, h, h, TOK, DD, HID);
    }

    ln_warp_kernel<<<(BB + 7) / 8, 256>>>(h, lnf_g, lnf_b, cls, (long)SS * DD, BB);
    head_kernel<<<BB, 128>>>(cls, head_w, out);
}